// round 12
// baseline (speedup 1.0000x reference)
#include <cuda_runtime.h>
#include <cuda_bf16.h>
#include <math.h>
#include <stdint.h>

#define Bdim 4
#define Sdim 2048
#define Hdim 512
#define NH   8
#define HD   64
#define H3   1536

// Static scratch (allocation-guard-safe)
__device__ uint32_t g_e_hi[(size_t)Bdim * NH * Sdim * Sdim / 2];  // bf16 pairs: exp(score) hi
__device__ uint32_t g_e_lo[(size_t)Bdim * NH * Sdim * Sdim / 2];  // bf16 pairs: exp(score) lo
__device__ float g_psum[(size_t)Bdim * NH * Sdim * 16];
__device__ float g_inv[(size_t)Bdim * NH * Sdim];
__device__ __nv_bfloat16 g_q_hi[(size_t)Bdim * NH * Sdim * HD];
__device__ __nv_bfloat16 g_q_lo[(size_t)Bdim * NH * Sdim * HD];
__device__ __nv_bfloat16 g_k_hi[(size_t)Bdim * NH * Sdim * HD];
__device__ __nv_bfloat16 g_k_lo[(size_t)Bdim * NH * Sdim * HD];
__device__ __nv_bfloat16 g_v_hi[(size_t)Bdim * Sdim * Hdim];
__device__ __nv_bfloat16 g_v_lo[(size_t)Bdim * Sdim * Hdim];
__device__ __nv_bfloat16 g_x_hi[(size_t)Bdim * Sdim * Hdim];
__device__ __nv_bfloat16 g_x_lo[(size_t)Bdim * Sdim * Hdim];
__device__ __nv_bfloat16 g_wqkv_hi[(size_t)H3 * Hdim];
__device__ __nv_bfloat16 g_wqkv_lo[(size_t)H3 * Hdim];
__device__ __nv_bfloat16 g_wout_hi[(size_t)Hdim * Hdim];
__device__ __nv_bfloat16 g_wout_lo[(size_t)Hdim * Hdim];
__device__ __nv_bfloat16 g_ctx_hi[(size_t)Bdim * Sdim * Hdim];
__device__ __nv_bfloat16 g_ctx_lo[(size_t)Bdim * Sdim * Hdim];

// ---- helpers ----------------------------------------------------------------
__device__ __forceinline__ uint32_t smem_u32(const void* p) {
    uint32_t a;
    asm("{ .reg .u64 t; cvta.to.shared.u64 t, %1; cvt.u32.u64 %0, t; }" : "=r"(a) : "l"(p));
    return a;
}
__device__ __forceinline__ void ldsm_x4(uint32_t* r, uint32_t addr) {
    asm volatile("ldmatrix.sync.aligned.m8n8.x4.shared.b16 {%0,%1,%2,%3}, [%4];"
                 : "=r"(r[0]), "=r"(r[1]), "=r"(r[2]), "=r"(r[3]) : "r"(addr));
}
__device__ __forceinline__ void ldsm_x2(uint32_t* r, uint32_t addr) {
    asm volatile("ldmatrix.sync.aligned.m8n8.x2.shared.b16 {%0,%1}, [%2];"
                 : "=r"(r[0]), "=r"(r[1]) : "r"(addr));
}
__device__ __forceinline__ void ldsm_x2t(uint32_t* r, uint32_t addr) {
    asm volatile("ldmatrix.sync.aligned.m8n8.x2.trans.shared.b16 {%0,%1}, [%2];"
                 : "=r"(r[0]), "=r"(r[1]) : "r"(addr));
}
__device__ __forceinline__ void mma_bf16(float* d, const uint32_t* a, const uint32_t* b) {
    asm volatile("mma.sync.aligned.m16n8k16.row.col.f32.bf16.bf16.f32 "
                 "{%0,%1,%2,%3}, {%4,%5,%6,%7}, {%8,%9}, {%0,%1,%2,%3};"
                 : "+f"(d[0]), "+f"(d[1]), "+f"(d[2]), "+f"(d[3])
                 : "r"(a[0]), "r"(a[1]), "r"(a[2]), "r"(a[3]), "r"(b[0]), "r"(b[1]));
}
__device__ __forceinline__ uint32_t pack_bf16x2(float e0, float e1) {
    uint32_t r;  // lower half = bf16(e0), upper = bf16(e1)
    asm("cvt.rn.bf16x2.f32 %0, %2, %1;" : "=r"(r) : "f"(e0), "f"(e1));
    return r;
}
__device__ __forceinline__ void cp_async16(uint32_t saddr, const void* gptr) {
    asm volatile("cp.async.cg.shared.global [%0], [%1], 16;" :: "r"(saddr), "l"(gptr));
}
#define CP_COMMIT() asm volatile("cp.async.commit_group;")
#define CP_WAITN(n) asm volatile("cp.async.wait_group %0;" :: "n"(n))

// ---------------------------------------------------------------------------
// K0: split fp32 -> bf16 hi/lo streams
// ---------------------------------------------------------------------------
__global__ void __launch_bounds__(256) split4_kernel(
    const float* __restrict__ src, __nv_bfloat16* __restrict__ hi,
    __nv_bfloat16* __restrict__ lo, int n4)
{
    int i = blockIdx.x * 256 + threadIdx.x;
    if (i >= n4) return;
    float4 v = ((const float4*)src)[i];
    uint32_t h01 = pack_bf16x2(v.x, v.y);
    uint32_t h23 = pack_bf16x2(v.z, v.w);
    float f0 = __uint_as_float(h01 << 16), f1 = __uint_as_float(h01 & 0xffff0000u);
    float f2 = __uint_as_float(h23 << 16), f3 = __uint_as_float(h23 & 0xffff0000u);
    uint32_t l01 = pack_bf16x2(v.x - f0, v.y - f1);
    uint32_t l23 = pack_bf16x2(v.z - f2, v.w - f3);
    ((uint2*)hi)[i] = make_uint2(h01, h23);
    ((uint2*)lo)[i] = make_uint2(l01, l23);
}

// ---------------------------------------------------------------------------
// K1/K5: bf16 3-term mma.sync GEMM, K=512. 3-stage cp.async pipeline.
// ---------------------------------------------------------------------------
#define GQ_SMEM (3 * 32768 + 512)

template<int MODE>
__global__ void __launch_bounds__(256, 2) gemm512_mma_kernel(
    const __nv_bfloat16* __restrict__ Ah, const __nv_bfloat16* __restrict__ Al,
    const __nv_bfloat16* __restrict__ Bh, const __nv_bfloat16* __restrict__ Bl,
    const float* __restrict__ bias, float* __restrict__ Cout, int Ncols)
{
    extern __shared__ __align__(16) char sm[];
    float* bias_s = (float*)(sm + 3 * 32768);

    const int tid = threadIdx.x, lane = tid & 31, wid = tid >> 5;
    const int m0 = blockIdx.y * 128, n0 = blockIdx.x * 128;
    const int wm = wid & 3, wn = wid >> 2;
    const uint32_t sb = smem_u32(sm);

    if (tid < 128) bias_s[tid] = bias[n0 + tid];

    float d[2][8][4];
#pragma unroll
    for (int mt = 0; mt < 2; mt++)
#pragma unroll
        for (int nt = 0; nt < 8; nt++)
#pragma unroll
            for (int e = 0; e < 4; e++) d[mt][nt][e] = 0.f;

#define GQ_CP(kc, st)                                                             \
    _Pragma("unroll") for (int i = 0; i < 2; i++) {                               \
        int idx = tid + 256 * i; int r = idx >> 2, cc = idx & 3;                  \
        uint32_t so = (uint32_t)(st) * 32768u + r * 64 +                          \
                      ((uint32_t)(cc ^ ((r >> 1) & 3)) << 4);                     \
        size_t ga = (size_t)(m0 + r) * 512 + (kc) + cc * 8;                       \
        size_t gb = (size_t)(n0 + r) * 512 + (kc) + cc * 8;                       \
        cp_async16(sb + so,         &Ah[ga]);                                     \
        cp_async16(sb + so + 8192,  &Al[ga]);                                     \
        cp_async16(sb + so + 16384, &Bh[gb]);                                     \
        cp_async16(sb + so + 24576, &Bl[gb]);                                     \
    }                                                                             \
    CP_COMMIT();

    GQ_CP(0, 0)
    GQ_CP(32, 1)

    for (int c = 0; c < 16; c++) {
        const int st = c % 3;
        if (c <= 14) { CP_WAITN(1); } else { CP_WAITN(0); }
        __syncthreads();
        if (c + 2 < 16) { GQ_CP((c + 2) * 32, (c + 2) % 3) }

        const uint32_t abase = sb + st * 32768;
        const uint32_t bbase = abase + 16384;
#pragma unroll
        for (int ks = 0; ks < 2; ks++) {
            uint32_t ah[2][4], al[2][4];
#pragma unroll
            for (int mt = 0; mt < 2; mt++) {
                int row = wm * 32 + mt * 16 + (lane & 15);
                int c16 = ks * 2 + (lane >> 4);
                uint32_t adr = abase + row * 64 + ((uint32_t)(c16 ^ ((row >> 1) & 3)) << 4);
                ldsm_x4(ah[mt], adr);
                ldsm_x4(al[mt], adr + 8192);
            }
            uint32_t bhf[8][2], blf[8][2];
#pragma unroll
            for (int p = 0; p < 4; p++) {
                int i4 = lane >> 3;
                int row = wn * 64 + p * 16 + (i4 & 1) * 8 + (lane & 7);
                int c16 = ks * 2 + (i4 >> 1);
                uint32_t adr = bbase + row * 64 + ((uint32_t)(c16 ^ ((row >> 1) & 3)) << 4);
                uint32_t t[4];
                ldsm_x4(t, adr);
                bhf[2 * p][0] = t[0]; bhf[2 * p][1] = t[2];
                bhf[2 * p + 1][0] = t[1]; bhf[2 * p + 1][1] = t[3];
                ldsm_x4(t, adr + 8192);
                blf[2 * p][0] = t[0]; blf[2 * p][1] = t[2];
                blf[2 * p + 1][0] = t[1]; blf[2 * p + 1][1] = t[3];
            }
#pragma unroll
            for (int mt = 0; mt < 2; mt++)
#pragma unroll
                for (int nt = 0; nt < 8; nt++)
                    mma_bf16(d[mt][nt], ah[mt], bhf[nt]);
#pragma unroll
            for (int mt = 0; mt < 2; mt++)
#pragma unroll
                for (int nt = 0; nt < 8; nt++)
                    mma_bf16(d[mt][nt], ah[mt], blf[nt]);
#pragma unroll
            for (int mt = 0; mt < 2; mt++)
#pragma unroll
                for (int nt = 0; nt < 8; nt++)
                    mma_bf16(d[mt][nt], al[mt], bhf[nt]);
        }
    }

    const int g = lane >> 2, tig = lane & 3;
#pragma unroll
    for (int mt = 0; mt < 2; mt++) {
#pragma unroll
        for (int hf = 0; hf < 2; hf++) {
            int m = m0 + wm * 32 + mt * 16 + hf * 8 + g;
            if (MODE == 0) {
                int b = m >> 11, s = m & 2047;
#pragma unroll
                for (int nt = 0; nt < 8; nt++) {
                    int cl = wn * 64 + nt * 8 + tig * 2;
                    int col = n0 + cl;
                    float e0 = d[mt][nt][hf * 2 + 0] + bias_s[cl];
                    float e1 = d[mt][nt][hf * 2 + 1] + bias_s[cl + 1];
                    uint32_t h01 = pack_bf16x2(e0, e1);
                    float f0 = __uint_as_float(h01 << 16);
                    float f1 = __uint_as_float(h01 & 0xffff0000u);
                    uint32_t l01 = pack_bf16x2(e0 - f0, e1 - f1);
                    int region = col >> 9;
                    int head = (col >> 6) & 7;
                    int d0 = col & 63;
                    if (region == 0) {
                        size_t off = ((size_t)(b * NH + head) * Sdim + s) * HD + d0;
                        *(uint32_t*)&g_q_hi[off] = h01;
                        *(uint32_t*)&g_q_lo[off] = l01;
                    } else if (region == 1) {
                        size_t off = ((size_t)(b * NH + head) * Sdim + s) * HD + d0;
                        *(uint32_t*)&g_k_hi[off] = h01;
                        *(uint32_t*)&g_k_lo[off] = l01;
                    } else {
                        size_t off = ((size_t)b * Sdim + s) * Hdim + (col - 1024);
                        *(uint32_t*)&g_v_hi[off] = h01;
                        *(uint32_t*)&g_v_lo[off] = l01;
                    }
                }
            } else {
                float* crow = Cout + (size_t)m * Ncols;
#pragma unroll
                for (int nt = 0; nt < 8; nt++) {
                    int cl = wn * 64 + nt * 8 + tig * 2;
                    float2 o = {d[mt][nt][hf * 2 + 0] + bias_s[cl],
                                d[mt][nt][hf * 2 + 1] + bias_s[cl + 1]};
                    *(float2*)&crow[n0 + cl] = o;
                }
            }
        }
    }
}

// ---------------------------------------------------------------------------
// K2: scores via mma.sync bf16 (3-term). e = exp2(C*(qk-d2))*maskflag.
// ---------------------------------------------------------------------------
#define SQS 72
#define SC_ARR (128 * SQS)
#define SC_SMEM (4 * SC_ARR * 2 + 2 * 128 * 16 + 128 * 2 * 4)
#define CLOG2E 0.1803368801111137f   // 0.125 * log2(e)

__global__ void __launch_bounds__(256, 2) scores_mma_kernel(
    const float* __restrict__ pos, const int* __restrict__ mask)
{
    extern __shared__ __align__(16) char sm[];
    __nv_bfloat16* Qh = (__nv_bfloat16*)sm;
    float4* Pq4 = (float4*)(sm + 4 * SC_ARR * 2);
    float4* Pk4 = Pq4 + 128;
    float* spart = (float*)(Pk4 + 128);

    const int tid = threadIdx.x, lane = tid & 31, wid = tid >> 5;
    const int bh = blockIdx.z, b = bh >> 3;
    const int q0 = blockIdx.y * 128, k0 = blockIdx.x * 128;
    const int kt = blockIdx.x;

    const __nv_bfloat16* sQh = g_q_hi + ((size_t)bh * Sdim + q0) * HD;
    const __nv_bfloat16* sQl = g_q_lo + ((size_t)bh * Sdim + q0) * HD;
    const __nv_bfloat16* sKh = g_k_hi + ((size_t)bh * Sdim + k0) * HD;
    const __nv_bfloat16* sKl = g_k_lo + ((size_t)bh * Sdim + k0) * HD;

    const uint32_t qb = smem_u32(Qh);
#pragma unroll
    for (int i = 0; i < 4; i++) {
        int idx = tid + 256 * i;
        int r = idx >> 3, c = idx & 7;
        uint32_t so = (r * SQS + c * 8) * 2;
        size_t go = (size_t)r * HD + c * 8;
        cp_async16(qb + so,                  &sQh[go]);
        cp_async16(qb + so + SC_ARR * 2,     &sQl[go]);
        cp_async16(qb + so + 2 * SC_ARR * 2, &sKh[go]);
        cp_async16(qb + so + 3 * SC_ARR * 2, &sKl[go]);
    }
    CP_COMMIT();

    if (tid < 128) {
        const float* pp = &pos[(size_t)(b * Sdim + q0 + tid) * 3];
        Pq4[tid] = make_float4(pp[0], pp[1], pp[2], 0.f);
    } else {
        int t2 = tid - 128;
        const float* pp = &pos[(size_t)(b * Sdim + k0 + t2) * 3];
        float mk = (mask[b * Sdim + k0 + t2] == 0) ? 0.f : 1.f;
        Pk4[t2] = make_float4(pp[0], pp[1], pp[2], mk);
    }
    CP_WAITN(0);
    __syncthreads();

    const int wm = wid & 3, wn = wid >> 2;
    const uint32_t kb = qb + 2 * SC_ARR * 2;
    const uint32_t LOFF = SC_ARR * 2;

    float d[2][8][4];
#pragma unroll
    for (int mt = 0; mt < 2; mt++)
#pragma unroll
        for (int nt = 0; nt < 8; nt++)
#pragma unroll
            for (int e = 0; e < 4; e++) d[mt][nt][e] = 0.f;

#pragma unroll
    for (int ks = 0; ks < 4; ks++) {
        uint32_t ah[2][4], al[2][4];
#pragma unroll
        for (int mt = 0; mt < 2; mt++) {
            int row = wm * 32 + mt * 16 + (lane & 15);
            int col = ks * 16 + (lane >> 4) * 8;
            uint32_t adr = qb + (row * SQS + col) * 2;
            ldsm_x4(ah[mt], adr);
            ldsm_x4(al[mt], adr + LOFF);
        }
        uint32_t bhf[8][2], blf[8][2];
#pragma unroll
        for (int nt = 0; nt < 8; nt++) {
            int row = wn * 64 + nt * 8 + (lane & 7);
            int col = ks * 16 + ((lane >> 3) & 1) * 8;
            uint32_t adr = kb + (row * SQS + col) * 2;
            ldsm_x2(bhf[nt], adr);
            ldsm_x2(blf[nt], adr + LOFF);
        }
#pragma unroll
        for (int mt = 0; mt < 2; mt++)
#pragma unroll
            for (int nt = 0; nt < 8; nt++)
                mma_bf16(d[mt][nt], ah[mt], bhf[nt]);
#pragma unroll
        for (int mt = 0; mt < 2; mt++)
#pragma unroll
            for (int nt = 0; nt < 8; nt++)
                mma_bf16(d[mt][nt], ah[mt], blf[nt]);
#pragma unroll
        for (int mt = 0; mt < 2; mt++)
#pragma unroll
            for (int nt = 0; nt < 8; nt++)
                mma_bf16(d[mt][nt], al[mt], bhf[nt]);
    }

    const int g = lane >> 2, tig = lane & 3;
#pragma unroll
    for (int mt = 0; mt < 2; mt++) {
#pragma unroll
        for (int hf = 0; hf < 2; hf++) {
            int lr = wm * 32 + mt * 16 + hf * 8 + g;
            float4 pq = Pq4[lr];
            uint32_t* hrow = g_e_hi + ((size_t)bh * Sdim + q0 + lr) * (Sdim / 2) + (k0 >> 1);
            uint32_t* lrow = g_e_lo + ((size_t)bh * Sdim + q0 + lr) * (Sdim / 2) + (k0 >> 1);
            float rsum = 0.f;
#pragma unroll
            for (int nt = 0; nt < 8; nt++) {
                int lc = wn * 64 + nt * 8 + tig * 2;
                float4 pk0 = Pk4[lc];
                float4 pk1 = Pk4[lc + 1];
                float v0 = d[mt][nt][hf * 2 + 0];
                float v1 = d[mt][nt][hf * 2 + 1];
                float dx0 = pq.x - pk0.x, dy0 = pq.y - pk0.y, dz0 = pq.z - pk0.z;
                float dx1 = pq.x - pk1.x, dy1 = pq.y - pk1.y, dz1 = pq.z - pk1.z;
                float s0 = (v0 - (dx0 * dx0 + dy0 * dy0 + dz0 * dz0)) * CLOG2E;
                float s1 = (v1 - (dx1 * dx1 + dy1 * dy1 + dz1 * dz1)) * CLOG2E;
                float e0 = exp2f(s0) * pk0.w;
                float e1 = exp2f(s1) * pk1.w;
                rsum += e0 + e1;
                uint32_t h01 = pack_bf16x2(e0, e1);
                float f0 = __uint_as_float(h01 << 16);
                float f1 = __uint_as_float(h01 & 0xffff0000u);
                uint32_t l01 = pack_bf16x2(e0 - f0, e1 - f1);
                hrow[lc >> 1] = h01;
                lrow[lc >> 1] = l01;
            }
            rsum += __shfl_xor_sync(0xffffffffu, rsum, 1);
            rsum += __shfl_xor_sync(0xffffffffu, rsum, 2);
            if (tig == 0) spart[lr * 2 + wn] = rsum;
        }
    }
    __syncthreads();
    if (tid < 128) {
        float ps = spart[tid * 2] + spart[tid * 2 + 1];
        g_psum[((size_t)bh * Sdim + q0 + tid) * 16 + kt] = ps;
    }
}

// ---------------------------------------------------------------------------
// K2b: inv = 1 / sum(16 partials)
// ---------------------------------------------------------------------------
__global__ void __launch_bounds__(256) rowsum_inv_kernel()
{
    int idx = blockIdx.x * 256 + threadIdx.x;
    const float* p = g_psum + (size_t)idx * 16;
    float s = 0.f;
#pragma unroll
    for (int i = 0; i < 16; i++) s += p[i];
    g_inv[idx] = 1.0f / s;
}

// ---------------------------------------------------------------------------
// K3: head-mean (pure stream)
// ---------------------------------------------------------------------------
__global__ void __launch_bounds__(256) mean_kernel(float* __restrict__ mean_out)
{
    const int bq = blockIdx.x;
    const int b = bq >> 11, q = bq & 2047;
    const int tid = threadIdx.x;
    const int pbase = tid * 4;

    __shared__ float inv_s[8];
    if (tid < 8) inv_s[tid] = g_inv[(size_t)(b * NH + tid) * Sdim + q];
    __syncthreads();

    float macc[8];
#pragma unroll
    for (int j = 0; j < 8; j++) macc[j] = 0.f;

#pragma unroll
    for (int h = 0; h < NH; h++) {
        size_t rb = ((size_t)((b * NH + h) * Sdim + q)) * (Sdim / 2);
        uint4 vh = *(const uint4*)&g_e_hi[rb + pbase];
        uint4 vl = *(const uint4*)&g_e_lo[rb + pbase];
        uint32_t hw[4] = {vh.x, vh.y, vh.z, vh.w};
        uint32_t lw[4] = {vl.x, vl.y, vl.z, vl.w};
        float invh = inv_s[h];
#pragma unroll
        for (int m = 0; m < 4; m++) {
            float e0 = __uint_as_float(hw[m] << 16) + __uint_as_float(lw[m] << 16);
            float e1 = __uint_as_float(hw[m] & 0xffff0000u) + __uint_as_float(lw[m] & 0xffff0000u);
            macc[2 * m]     = fmaf(e0, invh, macc[2 * m]);
            macc[2 * m + 1] = fmaf(e1, invh, macc[2 * m + 1]);
        }
    }

    float* mrow = mean_out + ((size_t)(b * Sdim + q)) * Sdim + tid * 8;
    float4 m0 = {macc[0] * 0.125f, macc[1] * 0.125f, macc[2] * 0.125f, macc[3] * 0.125f};
    float4 m1 = {macc[4] * 0.125f, macc[5] * 0.125f, macc[6] * 0.125f, macc[7] * 0.125f};
    *(float4*)&mrow[0] = m0;
    *(float4*)&mrow[4] = m1;
}

// ---------------------------------------------------------------------------
// K4: pv via mma.sync bf16 (3-term). 4-stage cp.async pipeline, 32-k chunks.
// Stage (24KB): Wh +0 (8K) | Wl +8K | Vh +16K (4K) | Vl +20K (4K)
// ---------------------------------------------------------------------------
#define PV_STAGE_B 24576
#define PV_WL_OFF  8192
#define PV_VH_OFF  16384
#define PV_VL_OFF  20480
#define PV_BASE    1024
#define PV_SMEM_B  (PV_BASE + 4 * PV_STAGE_B)   // 99328

__global__ void __launch_bounds__(256, 2) pv_mma_kernel()
{
    extern __shared__ __align__(16) char sm[];
    float* inv_s = (float*)sm;

    const int tid = threadIdx.x, lane = tid & 31, wid = tid >> 5;
    const int bh = blockIdx.y, b = bh >> 3, h = bh & 7;
    const int q0 = blockIdx.x * 128;

    const uint32_t* Eh = g_e_hi + ((size_t)bh * Sdim + q0) * (Sdim / 2);
    const uint32_t* El = g_e_lo + ((size_t)bh * Sdim + q0) * (Sdim / 2);
    const __nv_bfloat16* Vh_src = g_v_hi + (size_t)b * Sdim * Hdim + h * HD;
    const __nv_bfloat16* Vl_src = g_v_lo + (size_t)b * Sdim * Hdim + h * HD;

    const uint32_t sb = smem_u32(sm);
    const int wm = wid & 3, wn = wid >> 2;

    if (tid < 128)
        inv_s[tid] = g_inv[(size_t)bh * Sdim + q0 + tid];

    float d[2][4][4];
#pragma unroll
    for (int mt = 0; mt < 2; mt++)
#pragma unroll
        for (int nt = 0; nt < 4; nt++)
#pragma unroll
            for (int e = 0; e < 4; e++) d[mt][nt][e] = 0.f;

    // W chunk: 128 q-rows x 32 k bf16 per plane (64B rows, xor swizzle)
#define PV_CPW(kc, st)                                                            \
    _Pragma("unroll") for (int i = 0; i < 2; i++) {                               \
        int idx = tid + 256 * i; int r = idx >> 2, cc = idx & 3;                  \
        uint32_t soff = r * 64 + ((uint32_t)(cc ^ ((r >> 1) & 3)) << 4);          \
        uint32_t base = sb + PV_BASE + (st) * PV_STAGE_B;                         \
        size_t go = (size_t)r * (Sdim / 2) + ((kc) >> 1) + cc * 4;                \
        cp_async16(base + soff,             &Eh[go]);                             \
        cp_async16(base + PV_WL_OFF + soff, &El[go]);                             \
    }

    // V chunk: 32 k-rows x 64 d bf16 per plane (128B rows, kk&7 swizzle)
#define PV_CPV(kc, st)                                                            \
    {                                                                             \
        int kk = tid >> 3, c8 = tid & 7;                                          \
        uint32_t soff = kk * 128 + ((c8 * 16) ^ ((kk & 7) * 16));                 \
        uint32_t base = sb + PV_BASE + (st) * PV_STAGE_B;                         \
        cp_async16(base + PV_VH_OFF + soff, &Vh_src[(size_t)((kc) + kk) * Hdim + c8 * 8]); \
        cp_async16(base + PV_VL_OFF + soff, &Vl_src[(size_t)((kc) + kk) * Hdim + c8 * 8]); \
    }

    PV_CPW(0, 0)   PV_CPV(0, 0)   CP_COMMIT();
    PV_CPW(32, 1)  PV_CPV(32, 1)  CP_COMMIT();
    PV_CPW(64, 2)  PV_CPV(64, 2)  CP_COMMIT();

    for (int c = 0; c < 64; c++) {
        const int st = c & 3;
        if (c <= 61)      { CP_WAITN(2); }
        else if (c == 62) { CP_WAITN(1); }
        else              { CP_WAITN(0); }
        __syncthreads();
        if (c + 3 < 64) {
            PV_CPW((c + 3) * 32, (c + 3) & 3)
            PV_CPV((c + 3) * 32, (c + 3) & 3)
            CP_COMMIT();
        }
        {
            const uint32_t wbase = sb + PV_BASE + st * PV_STAGE_B;
            const uint32_t vbase = wbase + PV_VH_OFF;
#pragma unroll
            for (int ks = 0; ks < 2; ks++) {
                uint32_t ah[2][4], al[2][4];
#pragma unroll
                for (int mt = 0; mt < 2; mt++) {
                    int row = wm * 32 + mt * 16 + (lane & 15);
                    int c16 = ks * 2 + (lane >> 4);
                    uint32_t adr = wbase + row * 64 + ((uint32_t)(c16 ^ ((row >> 1) & 3)) << 4);
                    ldsm_x4(ah[mt], adr);
                    ldsm_x4(al[mt], adr + PV_WL_OFF);
                }
                uint32_t bhf[4][2], blf[4][2];
#pragma unroll
                for (int nt = 0; nt < 4; nt++) {
                    int rowk = ks * 16 + (lane & 15);
                    uint32_t colb = (wn * 32 + nt * 8) * 2;
                    uint32_t adr = vbase + rowk * 128 + (colb ^ ((rowk & 7) * 16));
                    ldsm_x2t(bhf[nt], adr);
                    ldsm_x2t(blf[nt], adr + (PV_VL_OFF - PV_VH_OFF));
                }
#pragma unroll
                for (int mt = 0; mt < 2; mt++)
#pragma unroll
                    for (int nt = 0; nt < 4; nt++)
                        mma_bf16(d[mt][nt], ah[mt], bhf[nt]);
#pragma unroll
                for (int mt = 0; mt < 2; mt++)
#pragma unroll
                    for (int nt = 0; nt < 4; nt++)
                        mma_bf16(d[mt][nt], ah[mt], blf[nt]);
#pragma unroll
                for (int mt = 0; mt < 2; mt++)
#pragma unroll
                    for (int nt = 0; nt < 4; nt++)
                        mma_bf16(d[mt][nt], al[mt], bhf[nt]);
            }
        }
    }

    const int g = lane >> 2, tig = lane & 3;
#pragma unroll
    for (int mt = 0; mt < 2; mt++)
#pragma unroll
        for (int nt = 0; nt < 4; nt++)
#pragma unroll
            for (int hf = 0; hf < 2; hf++) {
                int lr = wm * 32 + mt * 16 + g + hf * 8;
                float inv = inv_s[lr];
                int m = q0 + lr;
                int col = h * HD + wn * 32 + nt * 8 + tig * 2;
                float e0 = d[mt][nt][hf * 2 + 0] * inv;
                float e1 = d[mt][nt][hf * 2 + 1] * inv;
                uint32_t h01 = pack_bf16x2(e0, e1);
                float f0 = __uint_as_float(h01 << 16);
                float f1 = __uint_as_float(h01 & 0xffff0000u);
                uint32_t l01 = pack_bf16x2(e0 - f0, e1 - f1);
                size_t off = (size_t)(b * Sdim + m) * Hdim + col;
                *(uint32_t*)&g_ctx_hi[off] = h01;
                *(uint32_t*)&g_ctx_lo[off] = l01;
            }
}

// ---------------------------------------------------------------------------
extern "C" void kernel_launch(void* const* d_in, const int* in_sizes, int n_in,
                              void* d_out, int out_size)
{
    const float* x     = (const float*)d_in[0];
    const float* pos   = (const float*)d_in[1];
    const int*   mask  = (const int*)d_in[2];
    const float* w_qkv = (const float*)d_in[3];
    const float* b_qkv = (const float*)d_in[4];
    const float* w_out = (const float*)d_in[5];
    const float* b_out = (const float*)d_in[6];

    float* out_proj = (float*)d_out;
    float* mean_out = out_proj + (size_t)Bdim * Sdim * Hdim;

    __nv_bfloat16 *p_xh, *p_xl, *p_wqh, *p_wql, *p_woh, *p_wol, *p_ch, *p_cl;
    cudaGetSymbolAddress((void**)&p_xh, g_x_hi);
    cudaGetSymbolAddress((void**)&p_xl, g_x_lo);
    cudaGetSymbolAddress((void**)&p_wqh, g_wqkv_hi);
    cudaGetSymbolAddress((void**)&p_wql, g_wqkv_lo);
    cudaGetSymbolAddress((void**)&p_woh, g_wout_hi);
    cudaGetSymbolAddress((void**)&p_wol, g_wout_lo);
    cudaGetSymbolAddress((void**)&p_ch, g_ctx_hi);
    cudaGetSymbolAddress((void**)&p_cl, g_ctx_lo);

    static cudaStream_t s_side = nullptr;
    static cudaEvent_t ev_fork = nullptr, ev_join = nullptr;
    if (!s_side) {
        cudaStreamCreateWithFlags(&s_side, cudaStreamNonBlocking);
        cudaEventCreateWithFlags(&ev_fork, cudaEventDisableTiming);
        cudaEventCreateWithFlags(&ev_join, cudaEventDisableTiming);
        cudaFuncSetAttribute(gemm512_mma_kernel<0>, cudaFuncAttributeMaxDynamicSharedMemorySize, GQ_SMEM);
        cudaFuncSetAttribute(gemm512_mma_kernel<1>, cudaFuncAttributeMaxDynamicSharedMemorySize, GQ_SMEM);
        cudaFuncSetAttribute(scores_mma_kernel, cudaFuncAttributeMaxDynamicSharedMemorySize, SC_SMEM);
        cudaFuncSetAttribute(pv_mma_kernel, cudaFuncAttributeMaxDynamicSharedMemorySize, PV_SMEM_B);
    }

    // K0: pre-split fp32 inputs to bf16 hi/lo
    split4_kernel<<<(Bdim * Sdim * Hdim / 4 + 255) / 256, 256>>>(x, p_xh, p_xl, Bdim * Sdim * Hdim / 4);
    split4_kernel<<<(H3 * Hdim / 4 + 255) / 256, 256>>>(w_qkv, p_wqh, p_wql, H3 * Hdim / 4);
    split4_kernel<<<(Hdim * Hdim / 4 + 255) / 256, 256>>>(w_out, p_woh, p_wol, Hdim * Hdim / 4);

    // K1: QKV projection (tensor) + split scatter
    {
        dim3 grid(H3 / 128, (Bdim * Sdim) / 128);
        gemm512_mma_kernel<0><<<grid, 256, GQ_SMEM>>>(p_xh, p_xl, p_wqh, p_wql, b_qkv, nullptr, H3);
    }
    // K2: scores -> exp hi/lo planes + partial sums
    {
        dim3 grid(Sdim / 128, Sdim / 128, Bdim * NH);
        scores_mma_kernel<<<grid, 256, SC_SMEM>>>(pos, mask);
    }
    // K2b: row inverse sums
    rowsum_inv_kernel<<<(Bdim * NH * Sdim) / 256, 256>>>();

    // K4: pv gets the memory system to itself
    {
        dim3 grid(Sdim / 128, Bdim * NH);
        pv_mma_kernel<<<grid, 256, PV_SMEM_B>>>();
    }

    // fork: mean (DRAM-bound, side stream) overlaps out-proj (compute-bound, main)
    cudaEventRecord(ev_fork, 0);
    cudaStreamWaitEvent(s_side, ev_fork, 0);
    mean_kernel<<<Bdim * Sdim, 256, 0, s_side>>>(mean_out);
    cudaEventRecord(ev_join, s_side);

    // K5: output projection (tensor)
    {
        dim3 grid(Hdim / 128, (Bdim * Sdim) / 128);
        gemm512_mma_kernel<1><<<grid, 256, GQ_SMEM>>>(p_ch, p_cl, p_woh, p_wol, b_out, out_proj, Hdim);
    }
    // join
    cudaStreamWaitEvent(0, ev_join, 0);
}

// round 13
// speedup vs baseline: 1.2093x; 1.2093x over previous
#include <cuda_runtime.h>
#include <cuda_bf16.h>
#include <cuda_fp16.h>
#include <math.h>
#include <stdint.h>

#define Bdim 4
#define Sdim 2048
#define Hdim 512
#define NH   8
#define HD   64
#define H3   1536

// Static scratch (allocation-guard-safe)
__device__ uint32_t g_e[(size_t)Bdim * NH * Sdim * Sdim / 2];   // fp16 pairs: exp(score)
__device__ float g_psum[(size_t)Bdim * NH * Sdim * 16];
__device__ float g_inv[(size_t)Bdim * NH * Sdim];
__device__ __nv_bfloat16 g_q_hi[(size_t)Bdim * NH * Sdim * HD];
__device__ __nv_bfloat16 g_q_lo[(size_t)Bdim * NH * Sdim * HD];
__device__ __nv_bfloat16 g_k_hi[(size_t)Bdim * NH * Sdim * HD];
__device__ __nv_bfloat16 g_k_lo[(size_t)Bdim * NH * Sdim * HD];
__device__ __half g_v_hi[(size_t)Bdim * Sdim * Hdim];
__device__ __half g_v_lo[(size_t)Bdim * Sdim * Hdim];
__device__ __nv_bfloat16 g_x_hi[(size_t)Bdim * Sdim * Hdim];
__device__ __nv_bfloat16 g_x_lo[(size_t)Bdim * Sdim * Hdim];
__device__ __nv_bfloat16 g_wqkv_hi[(size_t)H3 * Hdim];
__device__ __nv_bfloat16 g_wqkv_lo[(size_t)H3 * Hdim];
__device__ __nv_bfloat16 g_wout_hi[(size_t)Hdim * Hdim];
__device__ __nv_bfloat16 g_wout_lo[(size_t)Hdim * Hdim];
__device__ __nv_bfloat16 g_ctx_hi[(size_t)Bdim * Sdim * Hdim];
__device__ __nv_bfloat16 g_ctx_lo[(size_t)Bdim * Sdim * Hdim];

// ---- helpers ----------------------------------------------------------------
__device__ __forceinline__ uint32_t smem_u32(const void* p) {
    uint32_t a;
    asm("{ .reg .u64 t; cvta.to.shared.u64 t, %1; cvt.u32.u64 %0, t; }" : "=r"(a) : "l"(p));
    return a;
}
__device__ __forceinline__ void ldsm_x4(uint32_t* r, uint32_t addr) {
    asm volatile("ldmatrix.sync.aligned.m8n8.x4.shared.b16 {%0,%1,%2,%3}, [%4];"
                 : "=r"(r[0]), "=r"(r[1]), "=r"(r[2]), "=r"(r[3]) : "r"(addr));
}
__device__ __forceinline__ void ldsm_x2(uint32_t* r, uint32_t addr) {
    asm volatile("ldmatrix.sync.aligned.m8n8.x2.shared.b16 {%0,%1}, [%2];"
                 : "=r"(r[0]), "=r"(r[1]) : "r"(addr));
}
__device__ __forceinline__ void ldsm_x2t(uint32_t* r, uint32_t addr) {
    asm volatile("ldmatrix.sync.aligned.m8n8.x2.trans.shared.b16 {%0,%1}, [%2];"
                 : "=r"(r[0]), "=r"(r[1]) : "r"(addr));
}
__device__ __forceinline__ void mma_bf16(float* d, const uint32_t* a, const uint32_t* b) {
    asm volatile("mma.sync.aligned.m16n8k16.row.col.f32.bf16.bf16.f32 "
                 "{%0,%1,%2,%3}, {%4,%5,%6,%7}, {%8,%9}, {%0,%1,%2,%3};"
                 : "+f"(d[0]), "+f"(d[1]), "+f"(d[2]), "+f"(d[3])
                 : "r"(a[0]), "r"(a[1]), "r"(a[2]), "r"(a[3]), "r"(b[0]), "r"(b[1]));
}
__device__ __forceinline__ void mma_f16(float* d, const uint32_t* a, const uint32_t* b) {
    asm volatile("mma.sync.aligned.m16n8k16.row.col.f32.f16.f16.f32 "
                 "{%0,%1,%2,%3}, {%4,%5,%6,%7}, {%8,%9}, {%0,%1,%2,%3};"
                 : "+f"(d[0]), "+f"(d[1]), "+f"(d[2]), "+f"(d[3])
                 : "r"(a[0]), "r"(a[1]), "r"(a[2]), "r"(a[3]), "r"(b[0]), "r"(b[1]));
}
__device__ __forceinline__ uint32_t pack_bf16x2(float e0, float e1) {
    uint32_t r;  // lower half = bf16(e0), upper = bf16(e1)
    asm("cvt.rn.bf16x2.f32 %0, %2, %1;" : "=r"(r) : "f"(e0), "f"(e1));
    return r;
}
__device__ __forceinline__ void cp_async16(uint32_t saddr, const void* gptr) {
    asm volatile("cp.async.cg.shared.global [%0], [%1], 16;" :: "r"(saddr), "l"(gptr));
}
#define CP_COMMIT() asm volatile("cp.async.commit_group;")
#define CP_WAIT0()  asm volatile("cp.async.wait_group 0;")

// ---------------------------------------------------------------------------
// K0: split fp32 -> bf16 hi/lo streams
// ---------------------------------------------------------------------------
__global__ void __launch_bounds__(256) split4_kernel(
    const float* __restrict__ src, __nv_bfloat16* __restrict__ hi,
    __nv_bfloat16* __restrict__ lo, int n4)
{
    int i = blockIdx.x * 256 + threadIdx.x;
    if (i >= n4) return;
    float4 v = ((const float4*)src)[i];
    uint32_t h01 = pack_bf16x2(v.x, v.y);
    uint32_t h23 = pack_bf16x2(v.z, v.w);
    float f0 = __uint_as_float(h01 << 16), f1 = __uint_as_float(h01 & 0xffff0000u);
    float f2 = __uint_as_float(h23 << 16), f3 = __uint_as_float(h23 & 0xffff0000u);
    uint32_t l01 = pack_bf16x2(v.x - f0, v.y - f1);
    uint32_t l23 = pack_bf16x2(v.z - f2, v.w - f3);
    ((uint2*)hi)[i] = make_uint2(h01, h23);
    ((uint2*)lo)[i] = make_uint2(l01, l23);
}

// ---------------------------------------------------------------------------
// K1/K5: bf16 3-term mma.sync GEMM, K=512. 2-stage pipeline (round-11 best).
// MODE 0: qkv epilogue (q/k -> bf16 hi/lo; v -> fp16 hi/lo). MODE 1: fp32+bias.
// ---------------------------------------------------------------------------
#define GQ_SMEM (65536 + 512)

template<int MODE>
__global__ void __launch_bounds__(256, 2) gemm512_mma_kernel(
    const __nv_bfloat16* __restrict__ Ah, const __nv_bfloat16* __restrict__ Al,
    const __nv_bfloat16* __restrict__ Bh, const __nv_bfloat16* __restrict__ Bl,
    const float* __restrict__ bias, float* __restrict__ Cout, int Ncols)
{
    extern __shared__ __align__(16) char sm[];
    float* bias_s = (float*)(sm + 65536);

    const int tid = threadIdx.x, lane = tid & 31, wid = tid >> 5;
    const int m0 = blockIdx.y * 128, n0 = blockIdx.x * 128;
    const int wm = wid & 3, wn = wid >> 2;
    const uint32_t sb = smem_u32(sm);

    if (tid < 128) bias_s[tid] = bias[n0 + tid];

    float d[2][8][4];
#pragma unroll
    for (int mt = 0; mt < 2; mt++)
#pragma unroll
        for (int nt = 0; nt < 8; nt++)
#pragma unroll
            for (int e = 0; e < 4; e++) d[mt][nt][e] = 0.f;

#define GQ_CP(kc, st)                                                             \
    _Pragma("unroll") for (int i = 0; i < 2; i++) {                               \
        int idx = tid + 256 * i; int r = idx >> 2, cc = idx & 3;                  \
        uint32_t so = (uint32_t)(st) * 32768u + r * 64 +                          \
                      ((uint32_t)(cc ^ ((r >> 1) & 3)) << 4);                     \
        size_t ga = (size_t)(m0 + r) * 512 + (kc) + cc * 8;                       \
        size_t gb = (size_t)(n0 + r) * 512 + (kc) + cc * 8;                       \
        cp_async16(sb + so,         &Ah[ga]);                                     \
        cp_async16(sb + so + 8192,  &Al[ga]);                                     \
        cp_async16(sb + so + 16384, &Bh[gb]);                                     \
        cp_async16(sb + so + 24576, &Bl[gb]);                                     \
    }                                                                             \
    CP_COMMIT();

    GQ_CP(0, 0)
    CP_WAIT0();
    __syncthreads();

    for (int c = 0; c < 16; c++) {
        const int st = c & 1;
        if (c < 15) { GQ_CP((c + 1) * 32, st ^ 1) }
        const uint32_t abase = sb + st * 32768;
        const uint32_t bbase = abase + 16384;
#pragma unroll
        for (int ks = 0; ks < 2; ks++) {
            uint32_t ah[2][4], al[2][4];
#pragma unroll
            for (int mt = 0; mt < 2; mt++) {
                int row = wm * 32 + mt * 16 + (lane & 15);
                int c16 = ks * 2 + (lane >> 4);
                uint32_t adr = abase + row * 64 + ((uint32_t)(c16 ^ ((row >> 1) & 3)) << 4);
                ldsm_x4(ah[mt], adr);
                ldsm_x4(al[mt], adr + 8192);
            }
            uint32_t bhf[8][2], blf[8][2];
#pragma unroll
            for (int p = 0; p < 4; p++) {
                int i4 = lane >> 3;
                int row = wn * 64 + p * 16 + (i4 & 1) * 8 + (lane & 7);
                int c16 = ks * 2 + (i4 >> 1);
                uint32_t adr = bbase + row * 64 + ((uint32_t)(c16 ^ ((row >> 1) & 3)) << 4);
                uint32_t t[4];
                ldsm_x4(t, adr);
                bhf[2 * p][0] = t[0]; bhf[2 * p][1] = t[2];
                bhf[2 * p + 1][0] = t[1]; bhf[2 * p + 1][1] = t[3];
                ldsm_x4(t, adr + 8192);
                blf[2 * p][0] = t[0]; blf[2 * p][1] = t[2];
                blf[2 * p + 1][0] = t[1]; blf[2 * p + 1][1] = t[3];
            }
#pragma unroll
            for (int mt = 0; mt < 2; mt++)
#pragma unroll
                for (int nt = 0; nt < 8; nt++)
                    mma_bf16(d[mt][nt], ah[mt], bhf[nt]);
#pragma unroll
            for (int mt = 0; mt < 2; mt++)
#pragma unroll
                for (int nt = 0; nt < 8; nt++)
                    mma_bf16(d[mt][nt], ah[mt], blf[nt]);
#pragma unroll
            for (int mt = 0; mt < 2; mt++)
#pragma unroll
                for (int nt = 0; nt < 8; nt++)
                    mma_bf16(d[mt][nt], al[mt], bhf[nt]);
        }
        if (c < 15) { CP_WAIT0(); }
        __syncthreads();
    }

    const int g = lane >> 2, tig = lane & 3;
#pragma unroll
    for (int mt = 0; mt < 2; mt++) {
#pragma unroll
        for (int hf = 0; hf < 2; hf++) {
            int m = m0 + wm * 32 + mt * 16 + hf * 8 + g;
            if (MODE == 0) {
                int b = m >> 11, s = m & 2047;
#pragma unroll
                for (int nt = 0; nt < 8; nt++) {
                    int cl = wn * 64 + nt * 8 + tig * 2;
                    int col = n0 + cl;
                    float e0 = d[mt][nt][hf * 2 + 0] + bias_s[cl];
                    float e1 = d[mt][nt][hf * 2 + 1] + bias_s[cl + 1];
                    int region = col >> 9;
                    if (region < 2) {
                        uint32_t h01 = pack_bf16x2(e0, e1);
                        float f0 = __uint_as_float(h01 << 16);
                        float f1 = __uint_as_float(h01 & 0xffff0000u);
                        uint32_t l01 = pack_bf16x2(e0 - f0, e1 - f1);
                        int head = (col >> 6) & 7;
                        int d0 = col & 63;
                        size_t off = ((size_t)(b * NH + head) * Sdim + s) * HD + d0;
                        if (region == 0) {
                            *(uint32_t*)&g_q_hi[off] = h01;
                            *(uint32_t*)&g_q_lo[off] = l01;
                        } else {
                            *(uint32_t*)&g_k_hi[off] = h01;
                            *(uint32_t*)&g_k_lo[off] = l01;
                        }
                    } else {
                        // V: fp16 hi/lo split
                        __half vh0 = __float2half_rn(e0), vh1 = __float2half_rn(e1);
                        float r0 = e0 - __half2float(vh0);
                        float r1 = e1 - __half2float(vh1);
                        __half vl0 = __float2half_rn(r0), vl1 = __float2half_rn(r1);
                        uint32_t h01 = ((uint32_t)__half_as_ushort(vh1) << 16) | __half_as_ushort(vh0);
                        uint32_t l01 = ((uint32_t)__half_as_ushort(vl1) << 16) | __half_as_ushort(vl0);
                        size_t off = ((size_t)b * Sdim + s) * Hdim + (col - 1024);
                        *(uint32_t*)&g_v_hi[off] = h01;
                        *(uint32_t*)&g_v_lo[off] = l01;
                    }
                }
            } else {
                float* crow = Cout + (size_t)m * Ncols;
#pragma unroll
                for (int nt = 0; nt < 8; nt++) {
                    int cl = wn * 64 + nt * 8 + tig * 2;
                    float2 o = {d[mt][nt][hf * 2 + 0] + bias_s[cl],
                                d[mt][nt][hf * 2 + 1] + bias_s[cl + 1]};
                    *(float2*)&crow[n0 + cl] = o;
                }
            }
        }
    }
}

// ---------------------------------------------------------------------------
// K2: scores via mma.sync bf16 (3-term). e = exp2(C*(qk-d2))*maskflag,
// stored as single fp16 plane; row sums computed from ROUNDED values.
// ---------------------------------------------------------------------------
#define SQS 72
#define SC_ARR (128 * SQS)
#define SC_SMEM (4 * SC_ARR * 2 + 2 * 128 * 16 + 128 * 2 * 4)
#define CLOG2E 0.1803368801111137f   // 0.125 * log2(e)

__global__ void __launch_bounds__(256, 2) scores_mma_kernel(
    const float* __restrict__ pos, const int* __restrict__ mask)
{
    extern __shared__ __align__(16) char sm[];
    __nv_bfloat16* Qh = (__nv_bfloat16*)sm;
    float4* Pq4 = (float4*)(sm + 4 * SC_ARR * 2);
    float4* Pk4 = Pq4 + 128;
    float* spart = (float*)(Pk4 + 128);

    const int tid = threadIdx.x, lane = tid & 31, wid = tid >> 5;
    const int bh = blockIdx.z, b = bh >> 3;
    const int q0 = blockIdx.y * 128, k0 = blockIdx.x * 128;
    const int kt = blockIdx.x;

    const __nv_bfloat16* sQh = g_q_hi + ((size_t)bh * Sdim + q0) * HD;
    const __nv_bfloat16* sQl = g_q_lo + ((size_t)bh * Sdim + q0) * HD;
    const __nv_bfloat16* sKh = g_k_hi + ((size_t)bh * Sdim + k0) * HD;
    const __nv_bfloat16* sKl = g_k_lo + ((size_t)bh * Sdim + k0) * HD;

    const uint32_t qb = smem_u32(Qh);
#pragma unroll
    for (int i = 0; i < 4; i++) {
        int idx = tid + 256 * i;
        int r = idx >> 3, c = idx & 7;
        uint32_t so = (r * SQS + c * 8) * 2;
        size_t go = (size_t)r * HD + c * 8;
        cp_async16(qb + so,                  &sQh[go]);
        cp_async16(qb + so + SC_ARR * 2,     &sQl[go]);
        cp_async16(qb + so + 2 * SC_ARR * 2, &sKh[go]);
        cp_async16(qb + so + 3 * SC_ARR * 2, &sKl[go]);
    }
    CP_COMMIT();

    if (tid < 128) {
        const float* pp = &pos[(size_t)(b * Sdim + q0 + tid) * 3];
        Pq4[tid] = make_float4(pp[0], pp[1], pp[2], 0.f);
    } else {
        int t2 = tid - 128;
        const float* pp = &pos[(size_t)(b * Sdim + k0 + t2) * 3];
        float mk = (mask[b * Sdim + k0 + t2] == 0) ? 0.f : 1.f;
        Pk4[t2] = make_float4(pp[0], pp[1], pp[2], mk);
    }
    CP_WAIT0();
    __syncthreads();

    const int wm = wid & 3, wn = wid >> 2;
    const uint32_t kb = qb + 2 * SC_ARR * 2;
    const uint32_t LOFF = SC_ARR * 2;

    float d[2][8][4];
#pragma unroll
    for (int mt = 0; mt < 2; mt++)
#pragma unroll
        for (int nt = 0; nt < 8; nt++)
#pragma unroll
            for (int e = 0; e < 4; e++) d[mt][nt][e] = 0.f;

#pragma unroll
    for (int ks = 0; ks < 4; ks++) {
        uint32_t ah[2][4], al[2][4];
#pragma unroll
        for (int mt = 0; mt < 2; mt++) {
            int row = wm * 32 + mt * 16 + (lane & 15);
            int col = ks * 16 + (lane >> 4) * 8;
            uint32_t adr = qb + (row * SQS + col) * 2;
            ldsm_x4(ah[mt], adr);
            ldsm_x4(al[mt], adr + LOFF);
        }
        uint32_t bhf[8][2], blf[8][2];
#pragma unroll
        for (int nt = 0; nt < 8; nt++) {
            int row = wn * 64 + nt * 8 + (lane & 7);
            int col = ks * 16 + ((lane >> 3) & 1) * 8;
            uint32_t adr = kb + (row * SQS + col) * 2;
            ldsm_x2(bhf[nt], adr);
            ldsm_x2(blf[nt], adr + LOFF);
        }
#pragma unroll
        for (int mt = 0; mt < 2; mt++)
#pragma unroll
            for (int nt = 0; nt < 8; nt++)
                mma_bf16(d[mt][nt], ah[mt], bhf[nt]);
#pragma unroll
        for (int mt = 0; mt < 2; mt++)
#pragma unroll
            for (int nt = 0; nt < 8; nt++)
                mma_bf16(d[mt][nt], ah[mt], blf[nt]);
#pragma unroll
        for (int mt = 0; mt < 2; mt++)
#pragma unroll
            for (int nt = 0; nt < 8; nt++)
                mma_bf16(d[mt][nt], al[mt], bhf[nt]);
    }

    const int g = lane >> 2, tig = lane & 3;
#pragma unroll
    for (int mt = 0; mt < 2; mt++) {
#pragma unroll
        for (int hf = 0; hf < 2; hf++) {
            int lr = wm * 32 + mt * 16 + hf * 8 + g;
            float4 pq = Pq4[lr];
            uint32_t* erow = g_e + ((size_t)bh * Sdim + q0 + lr) * (Sdim / 2) + (k0 >> 1);
            float rsum = 0.f;
#pragma unroll
            for (int nt = 0; nt < 8; nt++) {
                int lc = wn * 64 + nt * 8 + tig * 2;
                float4 pk0 = Pk4[lc];
                float4 pk1 = Pk4[lc + 1];
                float v0 = d[mt][nt][hf * 2 + 0];
                float v1 = d[mt][nt][hf * 2 + 1];
                float dx0 = pq.x - pk0.x, dy0 = pq.y - pk0.y, dz0 = pq.z - pk0.z;
                float dx1 = pq.x - pk1.x, dy1 = pq.y - pk1.y, dz1 = pq.z - pk1.z;
                float s0 = (v0 - (dx0 * dx0 + dy0 * dy0 + dz0 * dz0)) * CLOG2E;
                float s1 = (v1 - (dx1 * dx1 + dy1 * dy1 + dz1 * dz1)) * CLOG2E;
                float e0 = exp2f(s0) * pk0.w;
                float e1 = exp2f(s1) * pk1.w;
                __half hh0 = __float2half_rn(e0);
                __half hh1 = __float2half_rn(e1);
                // row sums from ROUNDED values -> weights sum to 1 exactly in expectation
                rsum += __half2float(hh0) + __half2float(hh1);
                erow[lc >> 1] = ((uint32_t)__half_as_ushort(hh1) << 16) | __half_as_ushort(hh0);
            }
            rsum += __shfl_xor_sync(0xffffffffu, rsum, 1);
            rsum += __shfl_xor_sync(0xffffffffu, rsum, 2);
            if (tig == 0) spart[lr * 2 + wn] = rsum;
        }
    }
    __syncthreads();
    if (tid < 128) {
        float ps = spart[tid * 2] + spart[tid * 2 + 1];
        g_psum[((size_t)bh * Sdim + q0 + tid) * 16 + kt] = ps;
    }
}

// ---------------------------------------------------------------------------
// K2b: inv = 1 / sum(16 partials)
// ---------------------------------------------------------------------------
__global__ void __launch_bounds__(256) rowsum_inv_kernel()
{
    int idx = blockIdx.x * 256 + threadIdx.x;
    const float* p = g_psum + (size_t)idx * 16;
    float s = 0.f;
#pragma unroll
    for (int i = 0; i < 16; i++) s += p[i];
    g_inv[idx] = 1.0f / s;
}

// ---------------------------------------------------------------------------
// K3: head-mean (pure stream) from single fp16 plane
// ---------------------------------------------------------------------------
__global__ void __launch_bounds__(256) mean_kernel(float* __restrict__ mean_out)
{
    const int bq = blockIdx.x;
    const int b = bq >> 11, q = bq & 2047;
    const int tid = threadIdx.x;
    const int pbase = tid * 4;

    __shared__ float inv_s[8];
    if (tid < 8) inv_s[tid] = g_inv[(size_t)(b * NH + tid) * Sdim + q];
    __syncthreads();

    float macc[8];
#pragma unroll
    for (int j = 0; j < 8; j++) macc[j] = 0.f;

#pragma unroll
    for (int h = 0; h < NH; h++) {
        size_t rb = ((size_t)((b * NH + h) * Sdim + q)) * (Sdim / 2);
        uint4 vw = *(const uint4*)&g_e[rb + pbase];
        uint32_t w[4] = {vw.x, vw.y, vw.z, vw.w};
        float invh = inv_s[h];
#pragma unroll
        for (int m = 0; m < 4; m++) {
            __half2 hp = *(__half2*)&w[m];
            float2 f = __half22float2(hp);
            macc[2 * m]     = fmaf(f.x, invh, macc[2 * m]);
            macc[2 * m + 1] = fmaf(f.y, invh, macc[2 * m + 1]);
        }
    }

    float* mrow = mean_out + ((size_t)(b * Sdim + q)) * Sdim + tid * 8;
    float4 m0 = {macc[0] * 0.125f, macc[1] * 0.125f, macc[2] * 0.125f, macc[3] * 0.125f};
    float4 m1 = {macc[4] * 0.125f, macc[5] * 0.125f, macc[6] * 0.125f, macc[7] * 0.125f};
    *(float4*)&mrow[0] = m0;
    *(float4*)&mrow[4] = m1;
}

// ---------------------------------------------------------------------------
// K4: pv via mma.sync fp16 (2-term): ctx = inv * (e @ (Vh + Vl)).
// e single fp16 plane, V fp16 hi/lo. 64-k chunks, 2 stages, 1 sync/chunk.
// Stage (32KB): W +0 (16KB) | Vh +16384 (8KB) | Vl +24576 (8KB)
// ---------------------------------------------------------------------------
#define PV_STAGE_B 32768
#define PV_VH_OFF  16384
#define PV_VL_OFF  24576
#define PV_BASE    1024
#define PV_SMEM_B  (PV_BASE + 2 * PV_STAGE_B)   // 66560

__global__ void __launch_bounds__(256, 2) pv_mma_kernel()
{
    extern __shared__ __align__(16) char sm[];
    float* inv_s = (float*)sm;

    const int tid = threadIdx.x, lane = tid & 31, wid = tid >> 5;
    const int bh = blockIdx.y, b = bh >> 3, h = bh & 7;
    const int q0 = blockIdx.x * 128;

    const uint32_t* Ep = g_e + ((size_t)bh * Sdim + q0) * (Sdim / 2);
    const __half* Vh_src = g_v_hi + (size_t)b * Sdim * Hdim + h * HD;
    const __half* Vl_src = g_v_lo + (size_t)b * Sdim * Hdim + h * HD;

    const uint32_t sb = smem_u32(sm);
    const int wm = wid & 3, wn = wid >> 2;

    if (tid < 128)
        inv_s[tid] = g_inv[(size_t)bh * Sdim + q0 + tid];

    float d[2][4][4];
#pragma unroll
    for (int mt = 0; mt < 2; mt++)
#pragma unroll
        for (int nt = 0; nt < 4; nt++)
#pragma unroll
            for (int e = 0; e < 4; e++) d[mt][nt][e] = 0.f;

    // W chunk: 128 q-rows x 64 k fp16 (128B rows, kk&7 xor swizzle)
#define PV_CPW(kc, st)                                                            \
    _Pragma("unroll") for (int i = 0; i < 4; i++) {                               \
        int idx = tid + 256 * i; int r = idx >> 3, cc = idx & 7;                  \
        uint32_t soff = r * 128 + ((cc * 16) ^ ((r & 7) * 16));                   \
        uint32_t base = sb + PV_BASE + (st) * PV_STAGE_B;                         \
        size_t go = (size_t)r * (Sdim / 2) + ((kc) >> 1) + cc * 4;                \
        cp_async16(base + soff, &Ep[go]);                                         \
    }

    // V chunk: 64 k-rows x 64 d fp16, hi+lo planes
#define PV_CPV(kc, st)                                                            \
    _Pragma("unroll") for (int i = 0; i < 2; i++) {                               \
        int idx = tid + 256 * i; int kk = idx >> 3, c8 = idx & 7;                 \
        uint32_t soff = kk * 128 + ((c8 * 16) ^ ((kk & 7) * 16));                 \
        uint32_t base = sb + PV_BASE + (st) * PV_STAGE_B;                         \
        cp_async16(base + PV_VH_OFF + soff, &Vh_src[(size_t)((kc) + kk) * Hdim + c8 * 8]); \
        cp_async16(base + PV_VL_OFF + soff, &Vl_src[(size_t)((kc) + kk) * Hdim + c8 * 8]); \
    }

    PV_CPW(0, 0)
    PV_CPV(0, 0)
    CP_COMMIT();
    CP_WAIT0();
    __syncthreads();

    for (int c = 0; c < 32; c++) {
        const int st = c & 1;
        if (c < 31) {
            PV_CPW((c + 1) * 64, st ^ 1)
            PV_CPV((c + 1) * 64, st ^ 1)
            CP_COMMIT();
        }
        {
            const uint32_t wbase = sb + PV_BASE + st * PV_STAGE_B;
            const uint32_t vbase = wbase + PV_VH_OFF;
#pragma unroll
            for (int ks = 0; ks < 4; ks++) {
                uint32_t aw[2][4];
#pragma unroll
                for (int mt = 0; mt < 2; mt++) {
                    int row = wm * 32 + mt * 16 + (lane & 15);
                    uint32_t colb = (ks * 16 + (lane >> 4) * 8) * 2;
                    uint32_t adr = wbase + row * 128 + (colb ^ ((row & 7) * 16));
                    ldsm_x4(aw[mt], adr);
                }
                uint32_t bhf[4][2], blf[4][2];
#pragma unroll
                for (int nt = 0; nt < 4; nt++) {
                    int rowk = ks * 16 + (lane & 15);
                    uint32_t colb = (wn * 32 + nt * 8) * 2;
                    uint32_t adr = vbase + rowk * 128 + (colb ^ ((rowk & 7) * 16));
                    ldsm_x2t(bhf[nt], adr);
                    ldsm_x2t(blf[nt], adr + (PV_VL_OFF - PV_VH_OFF));
                }
#pragma unroll
                for (int mt = 0; mt < 2; mt++)
#pragma unroll
                    for (int nt = 0; nt < 4; nt++)
                        mma_f16(d[mt][nt], aw[mt], bhf[nt]);
#pragma unroll
                for (int mt = 0; mt < 2; mt++)
#pragma unroll
                    for (int nt = 0; nt < 4; nt++)
                        mma_f16(d[mt][nt], aw[mt], blf[nt]);
            }
        }
        if (c < 31) { CP_WAIT0(); }
        __syncthreads();
    }

    const int g = lane >> 2, tig = lane & 3;
#pragma unroll
    for (int mt = 0; mt < 2; mt++)
#pragma unroll
        for (int nt = 0; nt < 4; nt++)
#pragma unroll
            for (int hf = 0; hf < 2; hf++) {
                int lr = wm * 32 + mt * 16 + g + hf * 8;
                float inv = inv_s[lr];
                int m = q0 + lr;
                int col = h * HD + wn * 32 + nt * 8 + tig * 2;
                float e0 = d[mt][nt][hf * 2 + 0] * inv;
                float e1 = d[mt][nt][hf * 2 + 1] * inv;
                uint32_t h01 = pack_bf16x2(e0, e1);
                float f0 = __uint_as_float(h01 << 16);
                float f1 = __uint_as_float(h01 & 0xffff0000u);
                uint32_t l01 = pack_bf16x2(e0 - f0, e1 - f1);
                size_t off = (size_t)(b * Sdim + m) * Hdim + col;
                *(uint32_t*)&g_ctx_hi[off] = h01;
                *(uint32_t*)&g_ctx_lo[off] = l01;
            }
}

// ---------------------------------------------------------------------------
extern "C" void kernel_launch(void* const* d_in, const int* in_sizes, int n_in,
                              void* d_out, int out_size)
{
    const float* x     = (const float*)d_in[0];
    const float* pos   = (const float*)d_in[1];
    const int*   mask  = (const int*)d_in[2];
    const float* w_qkv = (const float*)d_in[3];
    const float* b_qkv = (const float*)d_in[4];
    const float* w_out = (const float*)d_in[5];
    const float* b_out = (const float*)d_in[6];

    float* out_proj = (float*)d_out;
    float* mean_out = out_proj + (size_t)Bdim * Sdim * Hdim;

    __nv_bfloat16 *p_xh, *p_xl, *p_wqh, *p_wql, *p_woh, *p_wol, *p_ch, *p_cl;
    cudaGetSymbolAddress((void**)&p_xh, g_x_hi);
    cudaGetSymbolAddress((void**)&p_xl, g_x_lo);
    cudaGetSymbolAddress((void**)&p_wqh, g_wqkv_hi);
    cudaGetSymbolAddress((void**)&p_wql, g_wqkv_lo);
    cudaGetSymbolAddress((void**)&p_woh, g_wout_hi);
    cudaGetSymbolAddress((void**)&p_wol, g_wout_lo);
    cudaGetSymbolAddress((void**)&p_ch, g_ctx_hi);
    cudaGetSymbolAddress((void**)&p_cl, g_ctx_lo);

    static cudaStream_t s_side = nullptr;
    static cudaEvent_t ev_fork = nullptr, ev_join = nullptr;
    if (!s_side) {
        cudaStreamCreateWithFlags(&s_side, cudaStreamNonBlocking);
        cudaEventCreateWithFlags(&ev_fork, cudaEventDisableTiming);
        cudaEventCreateWithFlags(&ev_join, cudaEventDisableTiming);
        cudaFuncSetAttribute(gemm512_mma_kernel<0>, cudaFuncAttributeMaxDynamicSharedMemorySize, GQ_SMEM);
        cudaFuncSetAttribute(gemm512_mma_kernel<1>, cudaFuncAttributeMaxDynamicSharedMemorySize, GQ_SMEM);
        cudaFuncSetAttribute(scores_mma_kernel, cudaFuncAttributeMaxDynamicSharedMemorySize, SC_SMEM);
        cudaFuncSetAttribute(pv_mma_kernel, cudaFuncAttributeMaxDynamicSharedMemorySize, PV_SMEM_B);
    }

    // K0: pre-split fp32 inputs to bf16 hi/lo
    split4_kernel<<<(Bdim * Sdim * Hdim / 4 + 255) / 256, 256>>>(x, p_xh, p_xl, Bdim * Sdim * Hdim / 4);
    split4_kernel<<<(H3 * Hdim / 4 + 255) / 256, 256>>>(w_qkv, p_wqh, p_wql, H3 * Hdim / 4);
    split4_kernel<<<(Hdim * Hdim / 4 + 255) / 256, 256>>>(w_out, p_woh, p_wol, Hdim * Hdim / 4);

    // K1: QKV projection (tensor) + split scatter (q/k bf16, v fp16)
    {
        dim3 grid(H3 / 128, (Bdim * Sdim) / 128);
        gemm512_mma_kernel<0><<<grid, 256, GQ_SMEM>>>(p_xh, p_xl, p_wqh, p_wql, b_qkv, nullptr, H3);
    }
    // K2: scores -> exp fp16 plane + partial sums (over rounded values)
    {
        dim3 grid(Sdim / 128, Sdim / 128, Bdim * NH);
        scores_mma_kernel<<<grid, 256, SC_SMEM>>>(pos, mask);
    }
    // K2b: row inverse sums
    rowsum_inv_kernel<<<(Bdim * NH * Sdim) / 256, 256>>>();

    // K4: pv (fp16 2-term) gets the memory system to itself
    {
        dim3 grid(Sdim / 128, Bdim * NH);
        pv_mma_kernel<<<grid, 256, PV_SMEM_B>>>();
    }

    // fork: mean (DRAM-bound, side stream) overlaps out-proj (compute-bound, main)
    cudaEventRecord(ev_fork, 0);
    cudaStreamWaitEvent(s_side, ev_fork, 0);
    mean_kernel<<<Bdim * Sdim, 256, 0, s_side>>>(mean_out);
    cudaEventRecord(ev_join, s_side);

    // K5: output projection (tensor)
    {
        dim3 grid(Hdim / 128, (Bdim * Sdim) / 128);
        gemm512_mma_kernel<1><<<grid, 256, GQ_SMEM>>>(p_ch, p_cl, p_woh, p_wol, b_out, out_proj, Hdim);
    }
    // join
    cudaStreamWaitEvent(0, ev_join, 0);
}

// round 14
// speedup vs baseline: 1.4186x; 1.1731x over previous
#include <cuda_runtime.h>
#include <cuda_bf16.h>
#include <cuda_fp16.h>
#include <math.h>
#include <stdint.h>

#define Bdim 4
#define Sdim 2048
#define Hdim 512
#define NH   8
#define HD   64
#define H3   1536

// Static scratch (allocation-guard-safe)
__device__ uint32_t g_e[(size_t)Bdim * NH * Sdim * Sdim / 2];   // fp16 pairs: exp(score)
__device__ float g_psum[(size_t)Bdim * NH * Sdim * 16];
__device__ float g_inv[(size_t)Bdim * NH * Sdim];
__device__ __half g_q_hi[(size_t)Bdim * NH * Sdim * HD];
__device__ __half g_q_lo[(size_t)Bdim * NH * Sdim * HD];
__device__ __half g_k[(size_t)Bdim * NH * Sdim * HD];           // single fp16
__device__ __half g_v_hi[(size_t)Bdim * Sdim * Hdim];
__device__ __half g_v_lo[(size_t)Bdim * Sdim * Hdim];
__device__ __half g_x_hi[(size_t)Bdim * Sdim * Hdim];
__device__ __half g_x_lo[(size_t)Bdim * Sdim * Hdim];
__device__ __half g_wqkv[(size_t)H3 * Hdim];                    // single fp16
__device__ __half g_wout[(size_t)Hdim * Hdim];                  // single fp16
__device__ __half g_ctx_hi[(size_t)Bdim * Sdim * Hdim];
__device__ __half g_ctx_lo[(size_t)Bdim * Sdim * Hdim];

// ---- helpers ----------------------------------------------------------------
__device__ __forceinline__ uint32_t smem_u32(const void* p) {
    uint32_t a;
    asm("{ .reg .u64 t; cvta.to.shared.u64 t, %1; cvt.u32.u64 %0, t; }" : "=r"(a) : "l"(p));
    return a;
}
__device__ __forceinline__ void ldsm_x4(uint32_t* r, uint32_t addr) {
    asm volatile("ldmatrix.sync.aligned.m8n8.x4.shared.b16 {%0,%1,%2,%3}, [%4];"
                 : "=r"(r[0]), "=r"(r[1]), "=r"(r[2]), "=r"(r[3]) : "r"(addr));
}
__device__ __forceinline__ void ldsm_x2(uint32_t* r, uint32_t addr) {
    asm volatile("ldmatrix.sync.aligned.m8n8.x2.shared.b16 {%0,%1}, [%2];"
                 : "=r"(r[0]), "=r"(r[1]) : "r"(addr));
}
__device__ __forceinline__ void ldsm_x2t(uint32_t* r, uint32_t addr) {
    asm volatile("ldmatrix.sync.aligned.m8n8.x2.trans.shared.b16 {%0,%1}, [%2];"
                 : "=r"(r[0]), "=r"(r[1]) : "r"(addr));
}
__device__ __forceinline__ void mma_f16(float* d, const uint32_t* a, const uint32_t* b) {
    asm volatile("mma.sync.aligned.m16n8k16.row.col.f32.f16.f16.f32 "
                 "{%0,%1,%2,%3}, {%4,%5,%6,%7}, {%8,%9}, {%0,%1,%2,%3};"
                 : "+f"(d[0]), "+f"(d[1]), "+f"(d[2]), "+f"(d[3])
                 : "r"(a[0]), "r"(a[1]), "r"(a[2]), "r"(a[3]), "r"(b[0]), "r"(b[1]));
}
__device__ __forceinline__ uint32_t pack_f16x2(float a, float b) {
    __half2 h = __floats2half2_rn(a, b);
    return *(uint32_t*)&h;
}
__device__ __forceinline__ void cp_async16(uint32_t saddr, const void* gptr) {
    asm volatile("cp.async.cg.shared.global [%0], [%1], 16;" :: "r"(saddr), "l"(gptr));
}
#define CP_COMMIT() asm volatile("cp.async.commit_group;")
#define CP_WAIT0()  asm volatile("cp.async.wait_group 0;")

// ---------------------------------------------------------------------------
// K0a: split fp32 -> fp16 hi/lo planes
// ---------------------------------------------------------------------------
__global__ void __launch_bounds__(256) split4_f16_kernel(
    const float* __restrict__ src, __half* __restrict__ hi,
    __half* __restrict__ lo, int n4)
{
    int i = blockIdx.x * 256 + threadIdx.x;
    if (i >= n4) return;
    float4 v = ((const float4*)src)[i];
    __half h0 = __float2half_rn(v.x), h1 = __float2half_rn(v.y);
    __half h2 = __float2half_rn(v.z), h3 = __float2half_rn(v.w);
    float r0 = v.x - __half2float(h0), r1 = v.y - __half2float(h1);
    float r2 = v.z - __half2float(h2), r3 = v.w - __half2float(h3);
    uint32_t hi01 = ((uint32_t)__half_as_ushort(h1) << 16) | __half_as_ushort(h0);
    uint32_t hi23 = ((uint32_t)__half_as_ushort(h3) << 16) | __half_as_ushort(h2);
    ((uint2*)hi)[i] = make_uint2(hi01, hi23);
    ((uint2*)lo)[i] = make_uint2(pack_f16x2(r0, r1), pack_f16x2(r2, r3));
}

// K0b: convert fp32 -> single fp16 plane
__global__ void __launch_bounds__(256) conv4_f16_kernel(
    const float* __restrict__ src, __half* __restrict__ dst, int n4)
{
    int i = blockIdx.x * 256 + threadIdx.x;
    if (i >= n4) return;
    float4 v = ((const float4*)src)[i];
    ((uint2*)dst)[i] = make_uint2(pack_f16x2(v.x, v.y), pack_f16x2(v.z, v.w));
}

// ---------------------------------------------------------------------------
// K1/K5: fp16 2-term mma.sync GEMM, K=512: C = (Ah+Al) @ B^T + bias.
// Stage (24KB): Ah 8K | Al 8K | B 8K. 2 stages.
// MODE 0: qkv epilogue (q fp16 hi/lo, k fp16 single, v fp16 hi/lo).
// MODE 1: fp32 + bias out.
// ---------------------------------------------------------------------------
#define GQ_STAGE 24576
#define GQ_SMEM (2 * GQ_STAGE + 512)

template<int MODE>
__global__ void __launch_bounds__(256, 2) gemm512_mma_kernel(
    const __half* __restrict__ Ah, const __half* __restrict__ Al,
    const __half* __restrict__ B,
    const float* __restrict__ bias, float* __restrict__ Cout, int Ncols)
{
    extern __shared__ __align__(16) char sm[];
    float* bias_s = (float*)(sm + 2 * GQ_STAGE);

    const int tid = threadIdx.x, lane = tid & 31, wid = tid >> 5;
    const int m0 = blockIdx.y * 128, n0 = blockIdx.x * 128;
    const int wm = wid & 3, wn = wid >> 2;
    const uint32_t sb = smem_u32(sm);

    if (tid < 128) bias_s[tid] = bias[n0 + tid];

    float d[2][8][4];
#pragma unroll
    for (int mt = 0; mt < 2; mt++)
#pragma unroll
        for (int nt = 0; nt < 8; nt++)
#pragma unroll
            for (int e = 0; e < 4; e++) d[mt][nt][e] = 0.f;

#define GQ_CP(kc, st)                                                             \
    _Pragma("unroll") for (int i = 0; i < 2; i++) {                               \
        int idx = tid + 256 * i; int r = idx >> 2, cc = idx & 3;                  \
        uint32_t so = (uint32_t)(st) * GQ_STAGE + r * 64 +                        \
                      ((uint32_t)(cc ^ ((r >> 1) & 3)) << 4);                     \
        size_t ga = (size_t)(m0 + r) * 512 + (kc) + cc * 8;                       \
        size_t gb = (size_t)(n0 + r) * 512 + (kc) + cc * 8;                       \
        cp_async16(sb + so,         &Ah[ga]);                                     \
        cp_async16(sb + so + 8192,  &Al[ga]);                                     \
        cp_async16(sb + so + 16384, &B[gb]);                                      \
    }                                                                             \
    CP_COMMIT();

    GQ_CP(0, 0)
    CP_WAIT0();
    __syncthreads();

    for (int c = 0; c < 16; c++) {
        const int st = c & 1;
        if (c < 15) { GQ_CP((c + 1) * 32, st ^ 1) }
        const uint32_t abase = sb + st * GQ_STAGE;
        const uint32_t bbase = abase + 16384;
#pragma unroll
        for (int ks = 0; ks < 2; ks++) {
            uint32_t ah[2][4], al[2][4];
#pragma unroll
            for (int mt = 0; mt < 2; mt++) {
                int row = wm * 32 + mt * 16 + (lane & 15);
                int c16 = ks * 2 + (lane >> 4);
                uint32_t adr = abase + row * 64 + ((uint32_t)(c16 ^ ((row >> 1) & 3)) << 4);
                ldsm_x4(ah[mt], adr);
                ldsm_x4(al[mt], adr + 8192);
            }
            uint32_t bhf[8][2];
#pragma unroll
            for (int p = 0; p < 4; p++) {
                int i4 = lane >> 3;
                int row = wn * 64 + p * 16 + (i4 & 1) * 8 + (lane & 7);
                int c16 = ks * 2 + (i4 >> 1);
                uint32_t adr = bbase + row * 64 + ((uint32_t)(c16 ^ ((row >> 1) & 3)) << 4);
                uint32_t t[4];
                ldsm_x4(t, adr);
                bhf[2 * p][0] = t[0]; bhf[2 * p][1] = t[2];
                bhf[2 * p + 1][0] = t[1]; bhf[2 * p + 1][1] = t[3];
            }
#pragma unroll
            for (int mt = 0; mt < 2; mt++)
#pragma unroll
                for (int nt = 0; nt < 8; nt++)
                    mma_f16(d[mt][nt], ah[mt], bhf[nt]);
#pragma unroll
            for (int mt = 0; mt < 2; mt++)
#pragma unroll
                for (int nt = 0; nt < 8; nt++)
                    mma_f16(d[mt][nt], al[mt], bhf[nt]);
        }
        if (c < 15) { CP_WAIT0(); }
        __syncthreads();
    }

    const int g = lane >> 2, tig = lane & 3;
#pragma unroll
    for (int mt = 0; mt < 2; mt++) {
#pragma unroll
        for (int hf = 0; hf < 2; hf++) {
            int m = m0 + wm * 32 + mt * 16 + hf * 8 + g;
            if (MODE == 0) {
                int b = m >> 11, s = m & 2047;
#pragma unroll
                for (int nt = 0; nt < 8; nt++) {
                    int cl = wn * 64 + nt * 8 + tig * 2;
                    int col = n0 + cl;
                    float e0 = d[mt][nt][hf * 2 + 0] + bias_s[cl];
                    float e1 = d[mt][nt][hf * 2 + 1] + bias_s[cl + 1];
                    int region = col >> 9;
                    if (region == 0) {
                        // q: fp16 hi/lo
                        __half h0 = __float2half_rn(e0), h1 = __float2half_rn(e1);
                        float r0 = e0 - __half2float(h0);
                        float r1 = e1 - __half2float(h1);
                        uint32_t h01 = ((uint32_t)__half_as_ushort(h1) << 16) | __half_as_ushort(h0);
                        uint32_t l01 = pack_f16x2(r0, r1);
                        int head = (col >> 6) & 7;
                        int d0 = col & 63;
                        size_t off = ((size_t)(b * NH + head) * Sdim + s) * HD + d0;
                        *(uint32_t*)&g_q_hi[off] = h01;
                        *(uint32_t*)&g_q_lo[off] = l01;
                    } else if (region == 1) {
                        // k: single fp16
                        int head = (col >> 6) & 7;
                        int d0 = col & 63;
                        size_t off = ((size_t)(b * NH + head) * Sdim + s) * HD + d0;
                        *(uint32_t*)&g_k[off] = pack_f16x2(e0, e1);
                    } else {
                        // v: fp16 hi/lo
                        __half h0 = __float2half_rn(e0), h1 = __float2half_rn(e1);
                        float r0 = e0 - __half2float(h0);
                        float r1 = e1 - __half2float(h1);
                        uint32_t h01 = ((uint32_t)__half_as_ushort(h1) << 16) | __half_as_ushort(h0);
                        uint32_t l01 = pack_f16x2(r0, r1);
                        size_t off = ((size_t)b * Sdim + s) * Hdim + (col - 1024);
                        *(uint32_t*)&g_v_hi[off] = h01;
                        *(uint32_t*)&g_v_lo[off] = l01;
                    }
                }
            } else {
                float* crow = Cout + (size_t)m * Ncols;
#pragma unroll
                for (int nt = 0; nt < 8; nt++) {
                    int cl = wn * 64 + nt * 8 + tig * 2;
                    float2 o = {d[mt][nt][hf * 2 + 0] + bias_s[cl],
                                d[mt][nt][hf * 2 + 1] + bias_s[cl + 1]};
                    *(float2*)&crow[n0 + cl] = o;
                }
            }
        }
    }
}

// ---------------------------------------------------------------------------
// K2: scores via fp16 2-term mma.sync: s = (qh+ql)·k. e = exp2(C*(s-d2))*flag,
// single fp16 e plane; row sums from rounded values.
// ---------------------------------------------------------------------------
#define SQS 72
#define SC_ARR (128 * SQS)
#define SC_SMEM (3 * SC_ARR * 2 + 2 * 128 * 16 + 128 * 2 * 4)
#define CLOG2E 0.1803368801111137f   // 0.125 * log2(e)

__global__ void __launch_bounds__(256, 2) scores_mma_kernel(
    const float* __restrict__ pos, const int* __restrict__ mask)
{
    extern __shared__ __align__(16) char sm[];
    __half* Qh = (__half*)sm;
    float4* Pq4 = (float4*)(sm + 3 * SC_ARR * 2);
    float4* Pk4 = Pq4 + 128;
    float* spart = (float*)(Pk4 + 128);

    const int tid = threadIdx.x, lane = tid & 31, wid = tid >> 5;
    const int bh = blockIdx.z, b = bh >> 3;
    const int q0 = blockIdx.y * 128, k0 = blockIdx.x * 128;
    const int kt = blockIdx.x;

    const __half* sQh = g_q_hi + ((size_t)bh * Sdim + q0) * HD;
    const __half* sQl = g_q_lo + ((size_t)bh * Sdim + q0) * HD;
    const __half* sK  = g_k    + ((size_t)bh * Sdim + k0) * HD;

    const uint32_t qb = smem_u32(Qh);
#pragma unroll
    for (int i = 0; i < 4; i++) {
        int idx = tid + 256 * i;
        int r = idx >> 3, c = idx & 7;
        uint32_t so = (r * SQS + c * 8) * 2;
        size_t go = (size_t)r * HD + c * 8;
        cp_async16(qb + so,                  &sQh[go]);
        cp_async16(qb + so + SC_ARR * 2,     &sQl[go]);
        cp_async16(qb + so + 2 * SC_ARR * 2, &sK[go]);
    }
    CP_COMMIT();

    if (tid < 128) {
        const float* pp = &pos[(size_t)(b * Sdim + q0 + tid) * 3];
        Pq4[tid] = make_float4(pp[0], pp[1], pp[2], 0.f);
    } else {
        int t2 = tid - 128;
        const float* pp = &pos[(size_t)(b * Sdim + k0 + t2) * 3];
        float mk = (mask[b * Sdim + k0 + t2] == 0) ? 0.f : 1.f;
        Pk4[t2] = make_float4(pp[0], pp[1], pp[2], mk);
    }
    CP_WAIT0();
    __syncthreads();

    const int wm = wid & 3, wn = wid >> 2;
    const uint32_t kb = qb + 2 * SC_ARR * 2;
    const uint32_t LOFF = SC_ARR * 2;

    float d[2][8][4];
#pragma unroll
    for (int mt = 0; mt < 2; mt++)
#pragma unroll
        for (int nt = 0; nt < 8; nt++)
#pragma unroll
            for (int e = 0; e < 4; e++) d[mt][nt][e] = 0.f;

#pragma unroll
    for (int ks = 0; ks < 4; ks++) {
        uint32_t ah[2][4], al[2][4];
#pragma unroll
        for (int mt = 0; mt < 2; mt++) {
            int row = wm * 32 + mt * 16 + (lane & 15);
            int col = ks * 16 + (lane >> 4) * 8;
            uint32_t adr = qb + (row * SQS + col) * 2;
            ldsm_x4(ah[mt], adr);
            ldsm_x4(al[mt], adr + LOFF);
        }
        uint32_t bhf[8][2];
#pragma unroll
        for (int nt = 0; nt < 8; nt++) {
            int row = wn * 64 + nt * 8 + (lane & 7);
            int col = ks * 16 + ((lane >> 3) & 1) * 8;
            uint32_t adr = kb + (row * SQS + col) * 2;
            ldsm_x2(bhf[nt], adr);
        }
#pragma unroll
        for (int mt = 0; mt < 2; mt++)
#pragma unroll
            for (int nt = 0; nt < 8; nt++)
                mma_f16(d[mt][nt], ah[mt], bhf[nt]);
#pragma unroll
        for (int mt = 0; mt < 2; mt++)
#pragma unroll
            for (int nt = 0; nt < 8; nt++)
                mma_f16(d[mt][nt], al[mt], bhf[nt]);
    }

    const int g = lane >> 2, tig = lane & 3;
#pragma unroll
    for (int mt = 0; mt < 2; mt++) {
#pragma unroll
        for (int hf = 0; hf < 2; hf++) {
            int lr = wm * 32 + mt * 16 + hf * 8 + g;
            float4 pq = Pq4[lr];
            uint32_t* erow = g_e + ((size_t)bh * Sdim + q0 + lr) * (Sdim / 2) + (k0 >> 1);
            float rsum = 0.f;
#pragma unroll
            for (int nt = 0; nt < 8; nt++) {
                int lc = wn * 64 + nt * 8 + tig * 2;
                float4 pk0 = Pk4[lc];
                float4 pk1 = Pk4[lc + 1];
                float v0 = d[mt][nt][hf * 2 + 0];
                float v1 = d[mt][nt][hf * 2 + 1];
                float dx0 = pq.x - pk0.x, dy0 = pq.y - pk0.y, dz0 = pq.z - pk0.z;
                float dx1 = pq.x - pk1.x, dy1 = pq.y - pk1.y, dz1 = pq.z - pk1.z;
                float s0 = (v0 - (dx0 * dx0 + dy0 * dy0 + dz0 * dz0)) * CLOG2E;
                float s1 = (v1 - (dx1 * dx1 + dy1 * dy1 + dz1 * dz1)) * CLOG2E;
                float e0 = exp2f(s0) * pk0.w;
                float e1 = exp2f(s1) * pk1.w;
                __half hh0 = __float2half_rn(e0);
                __half hh1 = __float2half_rn(e1);
                rsum += __half2float(hh0) + __half2float(hh1);
                erow[lc >> 1] = ((uint32_t)__half_as_ushort(hh1) << 16) | __half_as_ushort(hh0);
            }
            rsum += __shfl_xor_sync(0xffffffffu, rsum, 1);
            rsum += __shfl_xor_sync(0xffffffffu, rsum, 2);
            if (tig == 0) spart[lr * 2 + wn] = rsum;
        }
    }
    __syncthreads();
    if (tid < 128) {
        float ps = spart[tid * 2] + spart[tid * 2 + 1];
        g_psum[((size_t)bh * Sdim + q0 + tid) * 16 + kt] = ps;
    }
}

// ---------------------------------------------------------------------------
// K2b: inv = 1 / sum(16 partials)
// ---------------------------------------------------------------------------
__global__ void __launch_bounds__(256) rowsum_inv_kernel()
{
    int idx = blockIdx.x * 256 + threadIdx.x;
    const float* p = g_psum + (size_t)idx * 16;
    float s = 0.f;
#pragma unroll
    for (int i = 0; i < 16; i++) s += p[i];
    g_inv[idx] = 1.0f / s;
}

// ---------------------------------------------------------------------------
// K3: head-mean (pure stream) from single fp16 plane
// ---------------------------------------------------------------------------
__global__ void __launch_bounds__(256) mean_kernel(float* __restrict__ mean_out)
{
    const int bq = blockIdx.x;
    const int b = bq >> 11, q = bq & 2047;
    const int tid = threadIdx.x;
    const int pbase = tid * 4;

    __shared__ float inv_s[8];
    if (tid < 8) inv_s[tid] = g_inv[(size_t)(b * NH + tid) * Sdim + q];
    __syncthreads();

    float macc[8];
#pragma unroll
    for (int j = 0; j < 8; j++) macc[j] = 0.f;

#pragma unroll
    for (int h = 0; h < NH; h++) {
        size_t rb = ((size_t)((b * NH + h) * Sdim + q)) * (Sdim / 2);
        uint4 vw = *(const uint4*)&g_e[rb + pbase];
        uint32_t w[4] = {vw.x, vw.y, vw.z, vw.w};
        float invh = inv_s[h];
#pragma unroll
        for (int m = 0; m < 4; m++) {
            __half2 hp = *(__half2*)&w[m];
            float2 f = __half22float2(hp);
            macc[2 * m]     = fmaf(f.x, invh, macc[2 * m]);
            macc[2 * m + 1] = fmaf(f.y, invh, macc[2 * m + 1]);
        }
    }

    float* mrow = mean_out + ((size_t)(b * Sdim + q)) * Sdim + tid * 8;
    float4 m0 = {macc[0] * 0.125f, macc[1] * 0.125f, macc[2] * 0.125f, macc[3] * 0.125f};
    float4 m1 = {macc[4] * 0.125f, macc[5] * 0.125f, macc[6] * 0.125f, macc[7] * 0.125f};
    *(float4*)&mrow[0] = m0;
    *(float4*)&mrow[4] = m1;
}

// ---------------------------------------------------------------------------
// K4: pv via fp16 2-term mma.sync: ctx = inv * (e @ (Vh + Vl)).
// Stage (32KB): W +0 (16KB) | Vh +16384 (8KB) | Vl +24576 (8KB)
// ctx written fp16 hi/lo.
// ---------------------------------------------------------------------------
#define PV_STAGE_B 32768
#define PV_VH_OFF  16384
#define PV_VL_OFF  24576
#define PV_BASE    1024
#define PV_SMEM_B  (PV_BASE + 2 * PV_STAGE_B)   // 66560

__global__ void __launch_bounds__(256, 2) pv_mma_kernel()
{
    extern __shared__ __align__(16) char sm[];
    float* inv_s = (float*)sm;

    const int tid = threadIdx.x, lane = tid & 31, wid = tid >> 5;
    const int bh = blockIdx.y, b = bh >> 3, h = bh & 7;
    const int q0 = blockIdx.x * 128;

    const uint32_t* Ep = g_e + ((size_t)bh * Sdim + q0) * (Sdim / 2);
    const __half* Vh_src = g_v_hi + (size_t)b * Sdim * Hdim + h * HD;
    const __half* Vl_src = g_v_lo + (size_t)b * Sdim * Hdim + h * HD;

    const uint32_t sb = smem_u32(sm);
    const int wm = wid & 3, wn = wid >> 2;

    if (tid < 128)
        inv_s[tid] = g_inv[(size_t)bh * Sdim + q0 + tid];

    float d[2][4][4];
#pragma unroll
    for (int mt = 0; mt < 2; mt++)
#pragma unroll
        for (int nt = 0; nt < 4; nt++)
#pragma unroll
            for (int e = 0; e < 4; e++) d[mt][nt][e] = 0.f;

#define PV_CPW(kc, st)                                                            \
    _Pragma("unroll") for (int i = 0; i < 4; i++) {                               \
        int idx = tid + 256 * i; int r = idx >> 3, cc = idx & 7;                  \
        uint32_t soff = r * 128 + ((cc * 16) ^ ((r & 7) * 16));                   \
        uint32_t base = sb + PV_BASE + (st) * PV_STAGE_B;                         \
        size_t go = (size_t)r * (Sdim / 2) + ((kc) >> 1) + cc * 4;                \
        cp_async16(base + soff, &Ep[go]);                                         \
    }

#define PV_CPV(kc, st)                                                            \
    _Pragma("unroll") for (int i = 0; i < 2; i++) {                               \
        int idx = tid + 256 * i; int kk = idx >> 3, c8 = idx & 7;                 \
        uint32_t soff = kk * 128 + ((c8 * 16) ^ ((kk & 7) * 16));                 \
        uint32_t base = sb + PV_BASE + (st) * PV_STAGE_B;                         \
        cp_async16(base + PV_VH_OFF + soff, &Vh_src[(size_t)((kc) + kk) * Hdim + c8 * 8]); \
        cp_async16(base + PV_VL_OFF + soff, &Vl_src[(size_t)((kc) + kk) * Hdim + c8 * 8]); \
    }

    PV_CPW(0, 0)
    PV_CPV(0, 0)
    CP_COMMIT();
    CP_WAIT0();
    __syncthreads();

    for (int c = 0; c < 32; c++) {
        const int st = c & 1;
        if (c < 31) {
            PV_CPW((c + 1) * 64, st ^ 1)
            PV_CPV((c + 1) * 64, st ^ 1)
            CP_COMMIT();
        }
        {
            const uint32_t wbase = sb + PV_BASE + st * PV_STAGE_B;
            const uint32_t vbase = wbase + PV_VH_OFF;
#pragma unroll
            for (int ks = 0; ks < 4; ks++) {
                uint32_t aw[2][4];
#pragma unroll
                for (int mt = 0; mt < 2; mt++) {
                    int row = wm * 32 + mt * 16 + (lane & 15);
                    uint32_t colb = (ks * 16 + (lane >> 4) * 8) * 2;
                    uint32_t adr = wbase + row * 128 + (colb ^ ((row & 7) * 16));
                    ldsm_x4(aw[mt], adr);
                }
                uint32_t bhf[4][2], blf[4][2];
#pragma unroll
                for (int nt = 0; nt < 4; nt++) {
                    int rowk = ks * 16 + (lane & 15);
                    uint32_t colb = (wn * 32 + nt * 8) * 2;
                    uint32_t adr = vbase + rowk * 128 + (colb ^ ((rowk & 7) * 16));
                    ldsm_x2t(bhf[nt], adr);
                    ldsm_x2t(blf[nt], adr + (PV_VL_OFF - PV_VH_OFF));
                }
#pragma unroll
                for (int mt = 0; mt < 2; mt++)
#pragma unroll
                    for (int nt = 0; nt < 4; nt++)
                        mma_f16(d[mt][nt], aw[mt], bhf[nt]);
#pragma unroll
                for (int mt = 0; mt < 2; mt++)
#pragma unroll
                    for (int nt = 0; nt < 4; nt++)
                        mma_f16(d[mt][nt], aw[mt], blf[nt]);
            }
        }
        if (c < 31) { CP_WAIT0(); }
        __syncthreads();
    }

    const int g = lane >> 2, tig = lane & 3;
#pragma unroll
    for (int mt = 0; mt < 2; mt++)
#pragma unroll
        for (int nt = 0; nt < 4; nt++)
#pragma unroll
            for (int hf = 0; hf < 2; hf++) {
                int lr = wm * 32 + mt * 16 + g + hf * 8;
                float inv = inv_s[lr];
                int m = q0 + lr;
                int col = h * HD + wn * 32 + nt * 8 + tig * 2;
                float e0 = d[mt][nt][hf * 2 + 0] * inv;
                float e1 = d[mt][nt][hf * 2 + 1] * inv;
                __half h0 = __float2half_rn(e0), h1 = __float2half_rn(e1);
                float r0 = e0 - __half2float(h0);
                float r1 = e1 - __half2float(h1);
                uint32_t h01 = ((uint32_t)__half_as_ushort(h1) << 16) | __half_as_ushort(h0);
                uint32_t l01 = pack_f16x2(r0, r1);
                size_t off = (size_t)(b * Sdim + m) * Hdim + col;
                *(uint32_t*)&g_ctx_hi[off] = h01;
                *(uint32_t*)&g_ctx_lo[off] = l01;
            }
}

// ---------------------------------------------------------------------------
extern "C" void kernel_launch(void* const* d_in, const int* in_sizes, int n_in,
                              void* d_out, int out_size)
{
    const float* x     = (const float*)d_in[0];
    const float* pos   = (const float*)d_in[1];
    const int*   mask  = (const int*)d_in[2];
    const float* w_qkv = (const float*)d_in[3];
    const float* b_qkv = (const float*)d_in[4];
    const float* w_out = (const float*)d_in[5];
    const float* b_out = (const float*)d_in[6];

    float* out_proj = (float*)d_out;
    float* mean_out = out_proj + (size_t)Bdim * Sdim * Hdim;

    __half *p_xh, *p_xl, *p_wq, *p_wo, *p_ch, *p_cl;
    cudaGetSymbolAddress((void**)&p_xh, g_x_hi);
    cudaGetSymbolAddress((void**)&p_xl, g_x_lo);
    cudaGetSymbolAddress((void**)&p_wq, g_wqkv);
    cudaGetSymbolAddress((void**)&p_wo, g_wout);
    cudaGetSymbolAddress((void**)&p_ch, g_ctx_hi);
    cudaGetSymbolAddress((void**)&p_cl, g_ctx_lo);

    static cudaStream_t s_side = nullptr;
    static cudaEvent_t ev_fork = nullptr, ev_join = nullptr;
    if (!s_side) {
        cudaStreamCreateWithFlags(&s_side, cudaStreamNonBlocking);
        cudaEventCreateWithFlags(&ev_fork, cudaEventDisableTiming);
        cudaEventCreateWithFlags(&ev_join, cudaEventDisableTiming);
        cudaFuncSetAttribute(gemm512_mma_kernel<0>, cudaFuncAttributeMaxDynamicSharedMemorySize, GQ_SMEM);
        cudaFuncSetAttribute(gemm512_mma_kernel<1>, cudaFuncAttributeMaxDynamicSharedMemorySize, GQ_SMEM);
        cudaFuncSetAttribute(scores_mma_kernel, cudaFuncAttributeMaxDynamicSharedMemorySize, SC_SMEM);
        cudaFuncSetAttribute(pv_mma_kernel, cudaFuncAttributeMaxDynamicSharedMemorySize, PV_SMEM_B);
    }

    // K0: pre-split / convert inputs to fp16
    split4_f16_kernel<<<(Bdim * Sdim * Hdim / 4 + 255) / 256, 256>>>(x, p_xh, p_xl, Bdim * Sdim * Hdim / 4);
    conv4_f16_kernel<<<(H3 * Hdim / 4 + 255) / 256, 256>>>(w_qkv, p_wq, H3 * Hdim / 4);
    conv4_f16_kernel<<<(Hdim * Hdim / 4 + 255) / 256, 256>>>(w_out, p_wo, Hdim * Hdim / 4);

    // K1: QKV projection (fp16 2-term) + scatter
    {
        dim3 grid(H3 / 128, (Bdim * Sdim) / 128);
        gemm512_mma_kernel<0><<<grid, 256, GQ_SMEM>>>(p_xh, p_xl, p_wq, b_qkv, nullptr, H3);
    }
    // K2: scores (fp16 2-term) -> exp fp16 plane + partial sums
    {
        dim3 grid(Sdim / 128, Sdim / 128, Bdim * NH);
        scores_mma_kernel<<<grid, 256, SC_SMEM>>>(pos, mask);
    }
    // K2b: row inverse sums
    rowsum_inv_kernel<<<(Bdim * NH * Sdim) / 256, 256>>>();

    // K4: pv (fp16 2-term)
    {
        dim3 grid(Sdim / 128, Bdim * NH);
        pv_mma_kernel<<<grid, 256, PV_SMEM_B>>>();
    }

    // fork: mean (DRAM-bound) overlaps out-proj (compute-bound)
    cudaEventRecord(ev_fork, 0);
    cudaStreamWaitEvent(s_side, ev_fork, 0);
    mean_kernel<<<Bdim * Sdim, 256, 0, s_side>>>(mean_out);
    cudaEventRecord(ev_join, s_side);

    // K5: output projection (fp16 2-term)
    {
        dim3 grid(Hdim / 128, (Bdim * Sdim) / 128);
        gemm512_mma_kernel<1><<<grid, 256, GQ_SMEM>>>(p_ch, p_cl, p_wo, b_out, out_proj, Hdim);
    }
    // join
    cudaStreamWaitEvent(0, ev_join, 0);
}

// round 15
// speedup vs baseline: 1.4986x; 1.0564x over previous
#include <cuda_runtime.h>
#include <cuda_bf16.h>
#include <cuda_fp16.h>
#include <math.h>
#include <stdint.h>

#define Bdim 4
#define Sdim 2048
#define Hdim 512
#define NH   8
#define HD   64
#define H3   1536

// Static scratch (allocation-guard-safe)
__device__ uint32_t g_e[(size_t)Bdim * NH * Sdim * Sdim / 2];   // fp16 pairs: exp(score)
__device__ float g_psum[(size_t)Bdim * NH * Sdim * 16];
__device__ float g_inv[(size_t)Bdim * NH * Sdim];
__device__ __half g_q_hi[(size_t)Bdim * NH * Sdim * HD];
__device__ __half g_q_lo[(size_t)Bdim * NH * Sdim * HD];
__device__ __half g_k[(size_t)Bdim * NH * Sdim * HD];           // single fp16
__device__ __half g_v_hi[(size_t)Bdim * Sdim * Hdim];
__device__ __half g_v_lo[(size_t)Bdim * Sdim * Hdim];
__device__ __half g_x_hi[(size_t)Bdim * Sdim * Hdim];
__device__ __half g_x_lo[(size_t)Bdim * Sdim * Hdim];
__device__ __half g_wqkv[(size_t)H3 * Hdim];                    // single fp16
__device__ __half g_wout[(size_t)Hdim * Hdim];                  // single fp16
__device__ __half g_ctx_hi[(size_t)Bdim * Sdim * Hdim];
__device__ __half g_ctx_lo[(size_t)Bdim * Sdim * Hdim];

// ---- helpers ----------------------------------------------------------------
__device__ __forceinline__ uint32_t smem_u32(const void* p) {
    uint32_t a;
    asm("{ .reg .u64 t; cvta.to.shared.u64 t, %1; cvt.u32.u64 %0, t; }" : "=r"(a) : "l"(p));
    return a;
}
__device__ __forceinline__ void ldsm_x4(uint32_t* r, uint32_t addr) {
    asm volatile("ldmatrix.sync.aligned.m8n8.x4.shared.b16 {%0,%1,%2,%3}, [%4];"
                 : "=r"(r[0]), "=r"(r[1]), "=r"(r[2]), "=r"(r[3]) : "r"(addr));
}
__device__ __forceinline__ void ldsm_x2(uint32_t* r, uint32_t addr) {
    asm volatile("ldmatrix.sync.aligned.m8n8.x2.shared.b16 {%0,%1}, [%2];"
                 : "=r"(r[0]), "=r"(r[1]) : "r"(addr));
}
__device__ __forceinline__ void ldsm_x2t(uint32_t* r, uint32_t addr) {
    asm volatile("ldmatrix.sync.aligned.m8n8.x2.trans.shared.b16 {%0,%1}, [%2];"
                 : "=r"(r[0]), "=r"(r[1]) : "r"(addr));
}
__device__ __forceinline__ void mma_f16(float* d, const uint32_t* a, const uint32_t* b) {
    asm volatile("mma.sync.aligned.m16n8k16.row.col.f32.f16.f16.f32 "
                 "{%0,%1,%2,%3}, {%4,%5,%6,%7}, {%8,%9}, {%0,%1,%2,%3};"
                 : "+f"(d[0]), "+f"(d[1]), "+f"(d[2]), "+f"(d[3])
                 : "r"(a[0]), "r"(a[1]), "r"(a[2]), "r"(a[3]), "r"(b[0]), "r"(b[1]));
}
__device__ __forceinline__ uint32_t pack_f16x2(float a, float b) {
    __half2 h = __floats2half2_rn(a, b);
    return *(uint32_t*)&h;
}
__device__ __forceinline__ void cp_async16(uint32_t saddr, const void* gptr) {
    asm volatile("cp.async.cg.shared.global [%0], [%1], 16;" :: "r"(saddr), "l"(gptr));
}
#define CP_COMMIT() asm volatile("cp.async.commit_group;")
#define CP_WAIT0()  asm volatile("cp.async.wait_group 0;")

// ---------------------------------------------------------------------------
// K0a: split fp32 -> fp16 hi/lo planes
// ---------------------------------------------------------------------------
__global__ void __launch_bounds__(256) split4_f16_kernel(
    const float* __restrict__ src, __half* __restrict__ hi,
    __half* __restrict__ lo, int n4)
{
    int i = blockIdx.x * 256 + threadIdx.x;
    if (i >= n4) return;
    float4 v = ((const float4*)src)[i];
    __half h0 = __float2half_rn(v.x), h1 = __float2half_rn(v.y);
    __half h2 = __float2half_rn(v.z), h3 = __float2half_rn(v.w);
    float r0 = v.x - __half2float(h0), r1 = v.y - __half2float(h1);
    float r2 = v.z - __half2float(h2), r3 = v.w - __half2float(h3);
    uint32_t hi01 = ((uint32_t)__half_as_ushort(h1) << 16) | __half_as_ushort(h0);
    uint32_t hi23 = ((uint32_t)__half_as_ushort(h3) << 16) | __half_as_ushort(h2);
    ((uint2*)hi)[i] = make_uint2(hi01, hi23);
    ((uint2*)lo)[i] = make_uint2(pack_f16x2(r0, r1), pack_f16x2(r2, r3));
}

// K0b: convert fp32 -> single fp16 plane
__global__ void __launch_bounds__(256) conv4_f16_kernel(
    const float* __restrict__ src, __half* __restrict__ dst, int n4)
{
    int i = blockIdx.x * 256 + threadIdx.x;
    if (i >= n4) return;
    float4 v = ((const float4*)src)[i];
    ((uint2*)dst)[i] = make_uint2(pack_f16x2(v.x, v.y), pack_f16x2(v.z, v.w));
}

// ---------------------------------------------------------------------------
// K1/K5: fp16 2-term mma.sync GEMM, K=512: C = (Ah+Al) @ B^T + bias.
// ---------------------------------------------------------------------------
#define GQ_STAGE 24576
#define GQ_SMEM (2 * GQ_STAGE + 512)

template<int MODE>
__global__ void __launch_bounds__(256, 2) gemm512_mma_kernel(
    const __half* __restrict__ Ah, const __half* __restrict__ Al,
    const __half* __restrict__ B,
    const float* __restrict__ bias, float* __restrict__ Cout, int Ncols)
{
    extern __shared__ __align__(16) char sm[];
    float* bias_s = (float*)(sm + 2 * GQ_STAGE);

    const int tid = threadIdx.x, lane = tid & 31, wid = tid >> 5;
    const int m0 = blockIdx.y * 128, n0 = blockIdx.x * 128;
    const int wm = wid & 3, wn = wid >> 2;
    const uint32_t sb = smem_u32(sm);

    if (tid < 128) bias_s[tid] = bias[n0 + tid];

    float d[2][8][4];
#pragma unroll
    for (int mt = 0; mt < 2; mt++)
#pragma unroll
        for (int nt = 0; nt < 8; nt++)
#pragma unroll
            for (int e = 0; e < 4; e++) d[mt][nt][e] = 0.f;

#define GQ_CP(kc, st)                                                             \
    _Pragma("unroll") for (int i = 0; i < 2; i++) {                               \
        int idx = tid + 256 * i; int r = idx >> 2, cc = idx & 3;                  \
        uint32_t so = (uint32_t)(st) * GQ_STAGE + r * 64 +                        \
                      ((uint32_t)(cc ^ ((r >> 1) & 3)) << 4);                     \
        size_t ga = (size_t)(m0 + r) * 512 + (kc) + cc * 8;                       \
        size_t gb = (size_t)(n0 + r) * 512 + (kc) + cc * 8;                       \
        cp_async16(sb + so,         &Ah[ga]);                                     \
        cp_async16(sb + so + 8192,  &Al[ga]);                                     \
        cp_async16(sb + so + 16384, &B[gb]);                                      \
    }                                                                             \
    CP_COMMIT();

    GQ_CP(0, 0)
    CP_WAIT0();
    __syncthreads();

    for (int c = 0; c < 16; c++) {
        const int st = c & 1;
        if (c < 15) { GQ_CP((c + 1) * 32, st ^ 1) }
        const uint32_t abase = sb + st * GQ_STAGE;
        const uint32_t bbase = abase + 16384;
#pragma unroll
        for (int ks = 0; ks < 2; ks++) {
            uint32_t ah[2][4], al[2][4];
#pragma unroll
            for (int mt = 0; mt < 2; mt++) {
                int row = wm * 32 + mt * 16 + (lane & 15);
                int c16 = ks * 2 + (lane >> 4);
                uint32_t adr = abase + row * 64 + ((uint32_t)(c16 ^ ((row >> 1) & 3)) << 4);
                ldsm_x4(ah[mt], adr);
                ldsm_x4(al[mt], adr + 8192);
            }
            uint32_t bhf[8][2];
#pragma unroll
            for (int p = 0; p < 4; p++) {
                int i4 = lane >> 3;
                int row = wn * 64 + p * 16 + (i4 & 1) * 8 + (lane & 7);
                int c16 = ks * 2 + (i4 >> 1);
                uint32_t adr = bbase + row * 64 + ((uint32_t)(c16 ^ ((row >> 1) & 3)) << 4);
                uint32_t t[4];
                ldsm_x4(t, adr);
                bhf[2 * p][0] = t[0]; bhf[2 * p][1] = t[2];
                bhf[2 * p + 1][0] = t[1]; bhf[2 * p + 1][1] = t[3];
            }
#pragma unroll
            for (int mt = 0; mt < 2; mt++)
#pragma unroll
                for (int nt = 0; nt < 8; nt++)
                    mma_f16(d[mt][nt], ah[mt], bhf[nt]);
#pragma unroll
            for (int mt = 0; mt < 2; mt++)
#pragma unroll
                for (int nt = 0; nt < 8; nt++)
                    mma_f16(d[mt][nt], al[mt], bhf[nt]);
        }
        if (c < 15) { CP_WAIT0(); }
        __syncthreads();
    }

    const int g = lane >> 2, tig = lane & 3;
#pragma unroll
    for (int mt = 0; mt < 2; mt++) {
#pragma unroll
        for (int hf = 0; hf < 2; hf++) {
            int m = m0 + wm * 32 + mt * 16 + hf * 8 + g;
            if (MODE == 0) {
                int b = m >> 11, s = m & 2047;
#pragma unroll
                for (int nt = 0; nt < 8; nt++) {
                    int cl = wn * 64 + nt * 8 + tig * 2;
                    int col = n0 + cl;
                    float e0 = d[mt][nt][hf * 2 + 0] + bias_s[cl];
                    float e1 = d[mt][nt][hf * 2 + 1] + bias_s[cl + 1];
                    int region = col >> 9;
                    if (region == 0) {
                        __half h0 = __float2half_rn(e0), h1 = __float2half_rn(e1);
                        float r0 = e0 - __half2float(h0);
                        float r1 = e1 - __half2float(h1);
                        uint32_t h01 = ((uint32_t)__half_as_ushort(h1) << 16) | __half_as_ushort(h0);
                        uint32_t l01 = pack_f16x2(r0, r1);
                        int head = (col >> 6) & 7;
                        int d0 = col & 63;
                        size_t off = ((size_t)(b * NH + head) * Sdim + s) * HD + d0;
                        *(uint32_t*)&g_q_hi[off] = h01;
                        *(uint32_t*)&g_q_lo[off] = l01;
                    } else if (region == 1) {
                        int head = (col >> 6) & 7;
                        int d0 = col & 63;
                        size_t off = ((size_t)(b * NH + head) * Sdim + s) * HD + d0;
                        *(uint32_t*)&g_k[off] = pack_f16x2(e0, e1);
                    } else {
                        __half h0 = __float2half_rn(e0), h1 = __float2half_rn(e1);
                        float r0 = e0 - __half2float(h0);
                        float r1 = e1 - __half2float(h1);
                        uint32_t h01 = ((uint32_t)__half_as_ushort(h1) << 16) | __half_as_ushort(h0);
                        uint32_t l01 = pack_f16x2(r0, r1);
                        size_t off = ((size_t)b * Sdim + s) * Hdim + (col - 1024);
                        *(uint32_t*)&g_v_hi[off] = h01;
                        *(uint32_t*)&g_v_lo[off] = l01;
                    }
                }
            } else {
                float* crow = Cout + (size_t)m * Ncols;
#pragma unroll
                for (int nt = 0; nt < 8; nt++) {
                    int cl = wn * 64 + nt * 8 + tig * 2;
                    float2 o = {d[mt][nt][hf * 2 + 0] + bias_s[cl],
                                d[mt][nt][hf * 2 + 1] + bias_s[cl + 1]};
                    *(float2*)&crow[n0 + cl] = o;
                }
            }
        }
    }
}

// ---------------------------------------------------------------------------
// K2: scores via fp16 2-term mma.sync; e single fp16 plane; sums from rounded.
// ---------------------------------------------------------------------------
#define SQS 72
#define SC_ARR (128 * SQS)
#define SC_SMEM (3 * SC_ARR * 2 + 2 * 128 * 16 + 128 * 2 * 4)
#define CLOG2E 0.1803368801111137f   // 0.125 * log2(e)

__global__ void __launch_bounds__(256, 2) scores_mma_kernel(
    const float* __restrict__ pos, const int* __restrict__ mask)
{
    extern __shared__ __align__(16) char sm[];
    __half* Qh = (__half*)sm;
    float4* Pq4 = (float4*)(sm + 3 * SC_ARR * 2);
    float4* Pk4 = Pq4 + 128;
    float* spart = (float*)(Pk4 + 128);

    const int tid = threadIdx.x, lane = tid & 31, wid = tid >> 5;
    const int bh = blockIdx.z, b = bh >> 3;
    const int q0 = blockIdx.y * 128, k0 = blockIdx.x * 128;
    const int kt = blockIdx.x;

    const __half* sQh = g_q_hi + ((size_t)bh * Sdim + q0) * HD;
    const __half* sQl = g_q_lo + ((size_t)bh * Sdim + q0) * HD;
    const __half* sK  = g_k    + ((size_t)bh * Sdim + k0) * HD;

    const uint32_t qb = smem_u32(Qh);
#pragma unroll
    for (int i = 0; i < 4; i++) {
        int idx = tid + 256 * i;
        int r = idx >> 3, c = idx & 7;
        uint32_t so = (r * SQS + c * 8) * 2;
        size_t go = (size_t)r * HD + c * 8;
        cp_async16(qb + so,                  &sQh[go]);
        cp_async16(qb + so + SC_ARR * 2,     &sQl[go]);
        cp_async16(qb + so + 2 * SC_ARR * 2, &sK[go]);
    }
    CP_COMMIT();

    if (tid < 128) {
        const float* pp = &pos[(size_t)(b * Sdim + q0 + tid) * 3];
        Pq4[tid] = make_float4(pp[0], pp[1], pp[2], 0.f);
    } else {
        int t2 = tid - 128;
        const float* pp = &pos[(size_t)(b * Sdim + k0 + t2) * 3];
        float mk = (mask[b * Sdim + k0 + t2] == 0) ? 0.f : 1.f;
        Pk4[t2] = make_float4(pp[0], pp[1], pp[2], mk);
    }
    CP_WAIT0();
    __syncthreads();

    const int wm = wid & 3, wn = wid >> 2;
    const uint32_t kb = qb + 2 * SC_ARR * 2;
    const uint32_t LOFF = SC_ARR * 2;

    float d[2][8][4];
#pragma unroll
    for (int mt = 0; mt < 2; mt++)
#pragma unroll
        for (int nt = 0; nt < 8; nt++)
#pragma unroll
            for (int e = 0; e < 4; e++) d[mt][nt][e] = 0.f;

#pragma unroll
    for (int ks = 0; ks < 4; ks++) {
        uint32_t ah[2][4], al[2][4];
#pragma unroll
        for (int mt = 0; mt < 2; mt++) {
            int row = wm * 32 + mt * 16 + (lane & 15);
            int col = ks * 16 + (lane >> 4) * 8;
            uint32_t adr = qb + (row * SQS + col) * 2;
            ldsm_x4(ah[mt], adr);
            ldsm_x4(al[mt], adr + LOFF);
        }
        uint32_t bhf[8][2];
#pragma unroll
        for (int nt = 0; nt < 8; nt++) {
            int row = wn * 64 + nt * 8 + (lane & 7);
            int col = ks * 16 + ((lane >> 3) & 1) * 8;
            uint32_t adr = kb + (row * SQS + col) * 2;
            ldsm_x2(bhf[nt], adr);
        }
#pragma unroll
        for (int mt = 0; mt < 2; mt++)
#pragma unroll
            for (int nt = 0; nt < 8; nt++)
                mma_f16(d[mt][nt], ah[mt], bhf[nt]);
#pragma unroll
        for (int mt = 0; mt < 2; mt++)
#pragma unroll
            for (int nt = 0; nt < 8; nt++)
                mma_f16(d[mt][nt], al[mt], bhf[nt]);
    }

    const int g = lane >> 2, tig = lane & 3;
#pragma unroll
    for (int mt = 0; mt < 2; mt++) {
#pragma unroll
        for (int hf = 0; hf < 2; hf++) {
            int lr = wm * 32 + mt * 16 + hf * 8 + g;
            float4 pq = Pq4[lr];
            uint32_t* erow = g_e + ((size_t)bh * Sdim + q0 + lr) * (Sdim / 2) + (k0 >> 1);
            float rsum = 0.f;
#pragma unroll
            for (int nt = 0; nt < 8; nt++) {
                int lc = wn * 64 + nt * 8 + tig * 2;
                float4 pk0 = Pk4[lc];
                float4 pk1 = Pk4[lc + 1];
                float v0 = d[mt][nt][hf * 2 + 0];
                float v1 = d[mt][nt][hf * 2 + 1];
                float dx0 = pq.x - pk0.x, dy0 = pq.y - pk0.y, dz0 = pq.z - pk0.z;
                float dx1 = pq.x - pk1.x, dy1 = pq.y - pk1.y, dz1 = pq.z - pk1.z;
                float s0 = (v0 - (dx0 * dx0 + dy0 * dy0 + dz0 * dz0)) * CLOG2E;
                float s1 = (v1 - (dx1 * dx1 + dy1 * dy1 + dz1 * dz1)) * CLOG2E;
                float e0 = exp2f(s0) * pk0.w;
                float e1 = exp2f(s1) * pk1.w;
                __half hh0 = __float2half_rn(e0);
                __half hh1 = __float2half_rn(e1);
                rsum += __half2float(hh0) + __half2float(hh1);
                erow[lc >> 1] = ((uint32_t)__half_as_ushort(hh1) << 16) | __half_as_ushort(hh0);
            }
            rsum += __shfl_xor_sync(0xffffffffu, rsum, 1);
            rsum += __shfl_xor_sync(0xffffffffu, rsum, 2);
            if (tig == 0) spart[lr * 2 + wn] = rsum;
        }
    }
    __syncthreads();
    if (tid < 128) {
        float ps = spart[tid * 2] + spart[tid * 2 + 1];
        g_psum[((size_t)bh * Sdim + q0 + tid) * 16 + kt] = ps;
    }
}

// ---------------------------------------------------------------------------
// K2b: inv = 1 / sum(16 partials)
// ---------------------------------------------------------------------------
__global__ void __launch_bounds__(256) rowsum_inv_kernel()
{
    int idx = blockIdx.x * 256 + threadIdx.x;
    const float* p = g_psum + (size_t)idx * 16;
    float s = 0.f;
#pragma unroll
    for (int i = 0; i < 16; i++) s += p[i];
    g_inv[idx] = 1.0f / s;
}

// ---------------------------------------------------------------------------
// K3: head-mean (pure stream) from single fp16 plane
// ---------------------------------------------------------------------------
__global__ void __launch_bounds__(256) mean_kernel(float* __restrict__ mean_out)
{
    const int bq = blockIdx.x;
    const int b = bq >> 11, q = bq & 2047;
    const int tid = threadIdx.x;
    const int pbase = tid * 4;

    __shared__ float inv_s[8];
    if (tid < 8) inv_s[tid] = g_inv[(size_t)(b * NH + tid) * Sdim + q];
    __syncthreads();

    float macc[8];
#pragma unroll
    for (int j = 0; j < 8; j++) macc[j] = 0.f;

#pragma unroll
    for (int h = 0; h < NH; h++) {
        size_t rb = ((size_t)((b * NH + h) * Sdim + q)) * (Sdim / 2);
        uint4 vw = *(const uint4*)&g_e[rb + pbase];
        uint32_t w[4] = {vw.x, vw.y, vw.z, vw.w};
        float invh = inv_s[h];
#pragma unroll
        for (int m = 0; m < 4; m++) {
            __half2 hp = *(__half2*)&w[m];
            float2 f = __half22float2(hp);
            macc[2 * m]     = fmaf(f.x, invh, macc[2 * m]);
            macc[2 * m + 1] = fmaf(f.y, invh, macc[2 * m + 1]);
        }
    }

    float* mrow = mean_out + ((size_t)(b * Sdim + q)) * Sdim + tid * 8;
    float4 m0 = {macc[0] * 0.125f, macc[1] * 0.125f, macc[2] * 0.125f, macc[3] * 0.125f};
    float4 m1 = {macc[4] * 0.125f, macc[5] * 0.125f, macc[6] * 0.125f, macc[7] * 0.125f};
    *(float4*)&mrow[0] = m0;
    *(float4*)&mrow[4] = m1;
}

// ---------------------------------------------------------------------------
// K4: pv via fp16 2-term mma.sync: ctx = inv * (e @ (Vh + Vl)).
// ---------------------------------------------------------------------------
#define PV_STAGE_B 32768
#define PV_VH_OFF  16384
#define PV_VL_OFF  24576
#define PV_BASE    1024
#define PV_SMEM_B  (PV_BASE + 2 * PV_STAGE_B)   // 66560

__global__ void __launch_bounds__(256, 2) pv_mma_kernel()
{
    extern __shared__ __align__(16) char sm[];
    float* inv_s = (float*)sm;

    const int tid = threadIdx.x, lane = tid & 31, wid = tid >> 5;
    const int bh = blockIdx.y, b = bh >> 3, h = bh & 7;
    const int q0 = blockIdx.x * 128;

    const uint32_t* Ep = g_e + ((size_t)bh * Sdim + q0) * (Sdim / 2);
    const __half* Vh_src = g_v_hi + (size_t)b * Sdim * Hdim + h * HD;
    const __half* Vl_src = g_v_lo + (size_t)b * Sdim * Hdim + h * HD;

    const uint32_t sb = smem_u32(sm);
    const int wm = wid & 3, wn = wid >> 2;

    if (tid < 128)
        inv_s[tid] = g_inv[(size_t)bh * Sdim + q0 + tid];

    float d[2][4][4];
#pragma unroll
    for (int mt = 0; mt < 2; mt++)
#pragma unroll
        for (int nt = 0; nt < 4; nt++)
#pragma unroll
            for (int e = 0; e < 4; e++) d[mt][nt][e] = 0.f;

#define PV_CPW(kc, st)                                                            \
    _Pragma("unroll") for (int i = 0; i < 4; i++) {                               \
        int idx = tid + 256 * i; int r = idx >> 3, cc = idx & 7;                  \
        uint32_t soff = r * 128 + ((cc * 16) ^ ((r & 7) * 16));                   \
        uint32_t base = sb + PV_BASE + (st) * PV_STAGE_B;                         \
        size_t go = (size_t)r * (Sdim / 2) + ((kc) >> 1) + cc * 4;                \
        cp_async16(base + soff, &Ep[go]);                                         \
    }

#define PV_CPV(kc, st)                                                            \
    _Pragma("unroll") for (int i = 0; i < 2; i++) {                               \
        int idx = tid + 256 * i; int kk = idx >> 3, c8 = idx & 7;                 \
        uint32_t soff = kk * 128 + ((c8 * 16) ^ ((kk & 7) * 16));                 \
        uint32_t base = sb + PV_BASE + (st) * PV_STAGE_B;                         \
        cp_async16(base + PV_VH_OFF + soff, &Vh_src[(size_t)((kc) + kk) * Hdim + c8 * 8]); \
        cp_async16(base + PV_VL_OFF + soff, &Vl_src[(size_t)((kc) + kk) * Hdim + c8 * 8]); \
    }

    PV_CPW(0, 0)
    PV_CPV(0, 0)
    CP_COMMIT();
    CP_WAIT0();
    __syncthreads();

    for (int c = 0; c < 32; c++) {
        const int st = c & 1;
        if (c < 31) {
            PV_CPW((c + 1) * 64, st ^ 1)
            PV_CPV((c + 1) * 64, st ^ 1)
            CP_COMMIT();
        }
        {
            const uint32_t wbase = sb + PV_BASE + st * PV_STAGE_B;
            const uint32_t vbase = wbase + PV_VH_OFF;
#pragma unroll
            for (int ks = 0; ks < 4; ks++) {
                uint32_t aw[2][4];
#pragma unroll
                for (int mt = 0; mt < 2; mt++) {
                    int row = wm * 32 + mt * 16 + (lane & 15);
                    uint32_t colb = (ks * 16 + (lane >> 4) * 8) * 2;
                    uint32_t adr = wbase + row * 128 + (colb ^ ((row & 7) * 16));
                    ldsm_x4(aw[mt], adr);
                }
                uint32_t bhf[4][2], blf[4][2];
#pragma unroll
                for (int nt = 0; nt < 4; nt++) {
                    int rowk = ks * 16 + (lane & 15);
                    uint32_t colb = (wn * 32 + nt * 8) * 2;
                    uint32_t adr = vbase + rowk * 128 + (colb ^ ((rowk & 7) * 16));
                    ldsm_x2t(bhf[nt], adr);
                    ldsm_x2t(blf[nt], adr + (PV_VL_OFF - PV_VH_OFF));
                }
#pragma unroll
                for (int mt = 0; mt < 2; mt++)
#pragma unroll
                    for (int nt = 0; nt < 4; nt++)
                        mma_f16(d[mt][nt], aw[mt], bhf[nt]);
#pragma unroll
                for (int mt = 0; mt < 2; mt++)
#pragma unroll
                    for (int nt = 0; nt < 4; nt++)
                        mma_f16(d[mt][nt], aw[mt], blf[nt]);
            }
        }
        if (c < 31) { CP_WAIT0(); }
        __syncthreads();
    }

    const int g = lane >> 2, tig = lane & 3;
#pragma unroll
    for (int mt = 0; mt < 2; mt++)
#pragma unroll
        for (int nt = 0; nt < 4; nt++)
#pragma unroll
            for (int hf = 0; hf < 2; hf++) {
                int lr = wm * 32 + mt * 16 + g + hf * 8;
                float inv = inv_s[lr];
                int m = q0 + lr;
                int col = h * HD + wn * 32 + nt * 8 + tig * 2;
                float e0 = d[mt][nt][hf * 2 + 0] * inv;
                float e1 = d[mt][nt][hf * 2 + 1] * inv;
                __half h0 = __float2half_rn(e0), h1 = __float2half_rn(e1);
                float r0 = e0 - __half2float(h0);
                float r1 = e1 - __half2float(h1);
                uint32_t h01 = ((uint32_t)__half_as_ushort(h1) << 16) | __half_as_ushort(h0);
                uint32_t l01 = pack_f16x2(r0, r1);
                size_t off = (size_t)(b * Sdim + m) * Hdim + col;
                *(uint32_t*)&g_ctx_hi[off] = h01;
                *(uint32_t*)&g_ctx_lo[off] = l01;
            }
}

// ---------------------------------------------------------------------------
extern "C" void kernel_launch(void* const* d_in, const int* in_sizes, int n_in,
                              void* d_out, int out_size)
{
    const float* x     = (const float*)d_in[0];
    const float* pos   = (const float*)d_in[1];
    const int*   mask  = (const int*)d_in[2];
    const float* w_qkv = (const float*)d_in[3];
    const float* b_qkv = (const float*)d_in[4];
    const float* w_out = (const float*)d_in[5];
    const float* b_out = (const float*)d_in[6];

    float* out_proj = (float*)d_out;
    float* mean_out = out_proj + (size_t)Bdim * Sdim * Hdim;

    __half *p_xh, *p_xl, *p_wq, *p_wo, *p_ch, *p_cl;
    cudaGetSymbolAddress((void**)&p_xh, g_x_hi);
    cudaGetSymbolAddress((void**)&p_xl, g_x_lo);
    cudaGetSymbolAddress((void**)&p_wq, g_wqkv);
    cudaGetSymbolAddress((void**)&p_wo, g_wout);
    cudaGetSymbolAddress((void**)&p_ch, g_ctx_hi);
    cudaGetSymbolAddress((void**)&p_cl, g_ctx_lo);

    static cudaStream_t s_side = nullptr;
    static cudaEvent_t ev_fork = nullptr, ev_join = nullptr;
    if (!s_side) {
        int prio_lo = 0, prio_hi = 0;
        cudaDeviceGetStreamPriorityRange(&prio_lo, &prio_hi);
        // prio_lo = numerically largest = LOWEST priority; mean should yield to pv
        cudaStreamCreateWithPriority(&s_side, cudaStreamNonBlocking, prio_lo);
        cudaEventCreateWithFlags(&ev_fork, cudaEventDisableTiming);
        cudaEventCreateWithFlags(&ev_join, cudaEventDisableTiming);
        cudaFuncSetAttribute(gemm512_mma_kernel<0>, cudaFuncAttributeMaxDynamicSharedMemorySize, GQ_SMEM);
        cudaFuncSetAttribute(gemm512_mma_kernel<1>, cudaFuncAttributeMaxDynamicSharedMemorySize, GQ_SMEM);
        cudaFuncSetAttribute(scores_mma_kernel, cudaFuncAttributeMaxDynamicSharedMemorySize, SC_SMEM);
        cudaFuncSetAttribute(pv_mma_kernel, cudaFuncAttributeMaxDynamicSharedMemorySize, PV_SMEM_B);
    }

    // K0: pre-split / convert inputs to fp16
    split4_f16_kernel<<<(Bdim * Sdim * Hdim / 4 + 255) / 256, 256>>>(x, p_xh, p_xl, Bdim * Sdim * Hdim / 4);
    conv4_f16_kernel<<<(H3 * Hdim / 4 + 255) / 256, 256>>>(w_qkv, p_wq, H3 * Hdim / 4);
    conv4_f16_kernel<<<(Hdim * Hdim / 4 + 255) / 256, 256>>>(w_out, p_wo, Hdim * Hdim / 4);

    // K1: QKV projection (fp16 2-term) + scatter
    {
        dim3 grid(H3 / 128, (Bdim * Sdim) / 128);
        gemm512_mma_kernel<0><<<grid, 256, GQ_SMEM>>>(p_xh, p_xl, p_wq, b_qkv, nullptr, H3);
    }
    // K2: scores (fp16 2-term) -> exp fp16 plane + partial sums
    {
        dim3 grid(Sdim / 128, Sdim / 128, Bdim * NH);
        scores_mma_kernel<<<grid, 256, SC_SMEM>>>(pos, mask);
    }
    // K2b: row inverse sums
    rowsum_inv_kernel<<<(Bdim * NH * Sdim) / 256, 256>>>();

    // fork point: both pv (main) and mean (side, LOW priority) depend on inv.
    cudaEventRecord(ev_fork, 0);
    cudaStreamWaitEvent(s_side, ev_fork, 0);

    // K4: pv launched FIRST (priority); mean backfills its spare bandwidth.
    {
        dim3 grid(Sdim / 128, Bdim * NH);
        pv_mma_kernel<<<grid, 256, PV_SMEM_B>>>();
    }
    mean_kernel<<<Bdim * Sdim, 256, 0, s_side>>>(mean_out);
    cudaEventRecord(ev_join, s_side);

    // K5: output projection (fp16 2-term)
    {
        dim3 grid(Hdim / 128, (Bdim * Sdim) / 128);
        gemm512_mma_kernel<1><<<grid, 256, GQ_SMEM>>>(p_ch, p_cl, p_wo, b_out, out_proj, Hdim);
    }
    // join
    cudaStreamWaitEvent(0, ev_join, 0);
}

// round 16
// speedup vs baseline: 1.8053x; 1.2046x over previous
#include <cuda_runtime.h>
#include <cuda_fp16.h>
#include <math.h>
#include <stdint.h>

#define Bdim 4
#define Sdim 2048
#define Hdim 512
#define NH   8
#define HD   64
#define H3   1536

// Static scratch (allocation-guard-safe)
__device__ uint32_t g_e[(size_t)Bdim * NH * Sdim * Sdim / 2];   // fp16 pairs: exp(score)
__device__ float g_psum[(size_t)Bdim * NH * Sdim * 16];
__device__ float g_inv[(size_t)Bdim * NH * Sdim];
__device__ __half g_q[(size_t)Bdim * NH * Sdim * HD];
__device__ __half g_k[(size_t)Bdim * NH * Sdim * HD];
__device__ __half g_v[(size_t)Bdim * Sdim * Hdim];
__device__ __half g_x[(size_t)Bdim * Sdim * Hdim];
__device__ __half g_wqkv[(size_t)H3 * Hdim];
__device__ __half g_wout[(size_t)Hdim * Hdim];
__device__ __half g_ctx[(size_t)Bdim * Sdim * Hdim];

// ---- helpers ----------------------------------------------------------------
__device__ __forceinline__ uint32_t smem_u32(const void* p) {
    uint32_t a;
    asm("{ .reg .u64 t; cvta.to.shared.u64 t, %1; cvt.u32.u64 %0, t; }" : "=r"(a) : "l"(p));
    return a;
}
__device__ __forceinline__ void ldsm_x4(uint32_t* r, uint32_t addr) {
    asm volatile("ldmatrix.sync.aligned.m8n8.x4.shared.b16 {%0,%1,%2,%3}, [%4];"
                 : "=r"(r[0]), "=r"(r[1]), "=r"(r[2]), "=r"(r[3]) : "r"(addr));
}
__device__ __forceinline__ void ldsm_x2(uint32_t* r, uint32_t addr) {
    asm volatile("ldmatrix.sync.aligned.m8n8.x2.shared.b16 {%0,%1}, [%2];"
                 : "=r"(r[0]), "=r"(r[1]) : "r"(addr));
}
__device__ __forceinline__ void ldsm_x2t(uint32_t* r, uint32_t addr) {
    asm volatile("ldmatrix.sync.aligned.m8n8.x2.trans.shared.b16 {%0,%1}, [%2];"
                 : "=r"(r[0]), "=r"(r[1]) : "r"(addr));
}
__device__ __forceinline__ void mma_f16(float* d, const uint32_t* a, const uint32_t* b) {
    asm volatile("mma.sync.aligned.m16n8k16.row.col.f32.f16.f16.f32 "
                 "{%0,%1,%2,%3}, {%4,%5,%6,%7}, {%8,%9}, {%0,%1,%2,%3};"
                 : "+f"(d[0]), "+f"(d[1]), "+f"(d[2]), "+f"(d[3])
                 : "r"(a[0]), "r"(a[1]), "r"(a[2]), "r"(a[3]), "r"(b[0]), "r"(b[1]));
}
__device__ __forceinline__ uint32_t pack_f16x2(float a, float b) {
    __half2 h = __floats2half2_rn(a, b);
    return *(uint32_t*)&h;
}
__device__ __forceinline__ void cp_async16(uint32_t saddr, const void* gptr) {
    asm volatile("cp.async.cg.shared.global [%0], [%1], 16;" :: "r"(saddr), "l"(gptr));
}
#define CP_COMMIT() asm volatile("cp.async.commit_group;")
#define CP_WAIT0()  asm volatile("cp.async.wait_group 0;")

// ---------------------------------------------------------------------------
// K0: convert fp32 -> single fp16 plane
// ---------------------------------------------------------------------------
__global__ void __launch_bounds__(256) conv4_f16_kernel(
    const float* __restrict__ src, __half* __restrict__ dst, int n4)
{
    int i = blockIdx.x * 256 + threadIdx.x;
    if (i >= n4) return;
    float4 v = ((const float4*)src)[i];
    ((uint2*)dst)[i] = make_uint2(pack_f16x2(v.x, v.y), pack_f16x2(v.z, v.w));
}

// ---------------------------------------------------------------------------
// K1/K5: plain fp16 1-term mma.sync GEMM, K=512: C = A @ B^T + bias.
// Stage (16KB): A 8K | B 8K. 2 stages.
// MODE 0: qkv epilogue (q/k/v single fp16 scatter). MODE 1: fp32 + bias out.
// ---------------------------------------------------------------------------
#define GQ_STAGE 16384
#define GQ_SMEM (2 * GQ_STAGE + 512)

template<int MODE>
__global__ void __launch_bounds__(256, 2) gemm512_mma_kernel(
    const __half* __restrict__ A, const __half* __restrict__ B,
    const float* __restrict__ bias, float* __restrict__ Cout, int Ncols)
{
    extern __shared__ __align__(16) char sm[];
    float* bias_s = (float*)(sm + 2 * GQ_STAGE);

    const int tid = threadIdx.x, lane = tid & 31, wid = tid >> 5;
    const int m0 = blockIdx.y * 128, n0 = blockIdx.x * 128;
    const int wm = wid & 3, wn = wid >> 2;
    const uint32_t sb = smem_u32(sm);

    if (tid < 128) bias_s[tid] = bias[n0 + tid];

    float d[2][8][4];
#pragma unroll
    for (int mt = 0; mt < 2; mt++)
#pragma unroll
        for (int nt = 0; nt < 8; nt++)
#pragma unroll
            for (int e = 0; e < 4; e++) d[mt][nt][e] = 0.f;

#define GQ_CP(kc, st)                                                             \
    _Pragma("unroll") for (int i = 0; i < 2; i++) {                               \
        int idx = tid + 256 * i; int r = idx >> 2, cc = idx & 3;                  \
        uint32_t so = (uint32_t)(st) * GQ_STAGE + r * 64 +                        \
                      ((uint32_t)(cc ^ ((r >> 1) & 3)) << 4);                     \
        size_t ga = (size_t)(m0 + r) * 512 + (kc) + cc * 8;                       \
        size_t gb = (size_t)(n0 + r) * 512 + (kc) + cc * 8;                       \
        cp_async16(sb + so,        &A[ga]);                                       \
        cp_async16(sb + so + 8192, &B[gb]);                                       \
    }                                                                             \
    CP_COMMIT();

    GQ_CP(0, 0)
    CP_WAIT0();
    __syncthreads();

    for (int c = 0; c < 16; c++) {
        const int st = c & 1;
        if (c < 15) { GQ_CP((c + 1) * 32, st ^ 1) }
        const uint32_t abase = sb + st * GQ_STAGE;
        const uint32_t bbase = abase + 8192;
#pragma unroll
        for (int ks = 0; ks < 2; ks++) {
            uint32_t ah[2][4];
#pragma unroll
            for (int mt = 0; mt < 2; mt++) {
                int row = wm * 32 + mt * 16 + (lane & 15);
                int c16 = ks * 2 + (lane >> 4);
                uint32_t adr = abase + row * 64 + ((uint32_t)(c16 ^ ((row >> 1) & 3)) << 4);
                ldsm_x4(ah[mt], adr);
            }
            uint32_t bhf[8][2];
#pragma unroll
            for (int p = 0; p < 4; p++) {
                int i4 = lane >> 3;
                int row = wn * 64 + p * 16 + (i4 & 1) * 8 + (lane & 7);
                int c16 = ks * 2 + (i4 >> 1);
                uint32_t adr = bbase + row * 64 + ((uint32_t)(c16 ^ ((row >> 1) & 3)) << 4);
                uint32_t t[4];
                ldsm_x4(t, adr);
                bhf[2 * p][0] = t[0]; bhf[2 * p][1] = t[2];
                bhf[2 * p + 1][0] = t[1]; bhf[2 * p + 1][1] = t[3];
            }
#pragma unroll
            for (int mt = 0; mt < 2; mt++)
#pragma unroll
                for (int nt = 0; nt < 8; nt++)
                    mma_f16(d[mt][nt], ah[mt], bhf[nt]);
        }
        if (c < 15) { CP_WAIT0(); }
        __syncthreads();
    }

    const int g = lane >> 2, tig = lane & 3;
#pragma unroll
    for (int mt = 0; mt < 2; mt++) {
#pragma unroll
        for (int hf = 0; hf < 2; hf++) {
            int m = m0 + wm * 32 + mt * 16 + hf * 8 + g;
            if (MODE == 0) {
                int b = m >> 11, s = m & 2047;
#pragma unroll
                for (int nt = 0; nt < 8; nt++) {
                    int cl = wn * 64 + nt * 8 + tig * 2;
                    int col = n0 + cl;
                    float e0 = d[mt][nt][hf * 2 + 0] + bias_s[cl];
                    float e1 = d[mt][nt][hf * 2 + 1] + bias_s[cl + 1];
                    uint32_t p01 = pack_f16x2(e0, e1);
                    int region = col >> 9;
                    if (region < 2) {
                        int head = (col >> 6) & 7;
                        int d0 = col & 63;
                        size_t off = ((size_t)(b * NH + head) * Sdim + s) * HD + d0;
                        if (region == 0) *(uint32_t*)&g_q[off] = p01;
                        else             *(uint32_t*)&g_k[off] = p01;
                    } else {
                        size_t off = ((size_t)b * Sdim + s) * Hdim + (col - 1024);
                        *(uint32_t*)&g_v[off] = p01;
                    }
                }
            } else {
                float* crow = Cout + (size_t)m * Ncols;
#pragma unroll
                for (int nt = 0; nt < 8; nt++) {
                    int cl = wn * 64 + nt * 8 + tig * 2;
                    float2 o = {d[mt][nt][hf * 2 + 0] + bias_s[cl],
                                d[mt][nt][hf * 2 + 1] + bias_s[cl + 1]};
                    *(float2*)&crow[n0 + cl] = o;
                }
            }
        }
    }
}

// ---------------------------------------------------------------------------
// K2: scores via plain fp16 1-term mma: s = q·k. e = exp2(C*(s-d2))*flag,
// single fp16 e plane; row sums from rounded values.
// ---------------------------------------------------------------------------
#define SQS 72
#define SC_ARR (128 * SQS)
#define SC_SMEM (2 * SC_ARR * 2 + 2 * 128 * 16 + 128 * 2 * 4)
#define CLOG2E 0.1803368801111137f   // 0.125 * log2(e)

__global__ void __launch_bounds__(256, 2) scores_mma_kernel(
    const float* __restrict__ pos, const int* __restrict__ mask)
{
    extern __shared__ __align__(16) char sm[];
    __half* Qs = (__half*)sm;
    float4* Pq4 = (float4*)(sm + 2 * SC_ARR * 2);
    float4* Pk4 = Pq4 + 128;
    float* spart = (float*)(Pk4 + 128);

    const int tid = threadIdx.x, lane = tid & 31, wid = tid >> 5;
    const int bh = blockIdx.z, b = bh >> 3;
    const int q0 = blockIdx.y * 128, k0 = blockIdx.x * 128;
    const int kt = blockIdx.x;

    const __half* sQ = g_q + ((size_t)bh * Sdim + q0) * HD;
    const __half* sK = g_k + ((size_t)bh * Sdim + k0) * HD;

    const uint32_t qb = smem_u32(Qs);
#pragma unroll
    for (int i = 0; i < 4; i++) {
        int idx = tid + 256 * i;
        int r = idx >> 3, c = idx & 7;
        uint32_t so = (r * SQS + c * 8) * 2;
        size_t go = (size_t)r * HD + c * 8;
        cp_async16(qb + so,              &sQ[go]);
        cp_async16(qb + so + SC_ARR * 2, &sK[go]);
    }
    CP_COMMIT();

    if (tid < 128) {
        const float* pp = &pos[(size_t)(b * Sdim + q0 + tid) * 3];
        Pq4[tid] = make_float4(pp[0], pp[1], pp[2], 0.f);
    } else {
        int t2 = tid - 128;
        const float* pp = &pos[(size_t)(b * Sdim + k0 + t2) * 3];
        float mk = (mask[b * Sdim + k0 + t2] == 0) ? 0.f : 1.f;
        Pk4[t2] = make_float4(pp[0], pp[1], pp[2], mk);
    }
    CP_WAIT0();
    __syncthreads();

    const int wm = wid & 3, wn = wid >> 2;
    const uint32_t kb = qb + SC_ARR * 2;

    float d[2][8][4];
#pragma unroll
    for (int mt = 0; mt < 2; mt++)
#pragma unroll
        for (int nt = 0; nt < 8; nt++)
#pragma unroll
            for (int e = 0; e < 4; e++) d[mt][nt][e] = 0.f;

#pragma unroll
    for (int ks = 0; ks < 4; ks++) {
        uint32_t ah[2][4];
#pragma unroll
        for (int mt = 0; mt < 2; mt++) {
            int row = wm * 32 + mt * 16 + (lane & 15);
            int col = ks * 16 + (lane >> 4) * 8;
            uint32_t adr = qb + (row * SQS + col) * 2;
            ldsm_x4(ah[mt], adr);
        }
        uint32_t bhf[8][2];
#pragma unroll
        for (int nt = 0; nt < 8; nt++) {
            int row = wn * 64 + nt * 8 + (lane & 7);
            int col = ks * 16 + ((lane >> 3) & 1) * 8;
            uint32_t adr = kb + (row * SQS + col) * 2;
            ldsm_x2(bhf[nt], adr);
        }
#pragma unroll
        for (int mt = 0; mt < 2; mt++)
#pragma unroll
            for (int nt = 0; nt < 8; nt++)
                mma_f16(d[mt][nt], ah[mt], bhf[nt]);
    }

    const int g = lane >> 2, tig = lane & 3;
#pragma unroll
    for (int mt = 0; mt < 2; mt++) {
#pragma unroll
        for (int hf = 0; hf < 2; hf++) {
            int lr = wm * 32 + mt * 16 + hf * 8 + g;
            float4 pq = Pq4[lr];
            uint32_t* erow = g_e + ((size_t)bh * Sdim + q0 + lr) * (Sdim / 2) + (k0 >> 1);
            float rsum = 0.f;
#pragma unroll
            for (int nt = 0; nt < 8; nt++) {
                int lc = wn * 64 + nt * 8 + tig * 2;
                float4 pk0 = Pk4[lc];
                float4 pk1 = Pk4[lc + 1];
                float v0 = d[mt][nt][hf * 2 + 0];
                float v1 = d[mt][nt][hf * 2 + 1];
                float dx0 = pq.x - pk0.x, dy0 = pq.y - pk0.y, dz0 = pq.z - pk0.z;
                float dx1 = pq.x - pk1.x, dy1 = pq.y - pk1.y, dz1 = pq.z - pk1.z;
                float s0 = (v0 - (dx0 * dx0 + dy0 * dy0 + dz0 * dz0)) * CLOG2E;
                float s1 = (v1 - (dx1 * dx1 + dy1 * dy1 + dz1 * dz1)) * CLOG2E;
                float e0 = exp2f(s0) * pk0.w;
                float e1 = exp2f(s1) * pk1.w;
                __half hh0 = __float2half_rn(e0);
                __half hh1 = __float2half_rn(e1);
                rsum += __half2float(hh0) + __half2float(hh1);
                erow[lc >> 1] = ((uint32_t)__half_as_ushort(hh1) << 16) | __half_as_ushort(hh0);
            }
            rsum += __shfl_xor_sync(0xffffffffu, rsum, 1);
            rsum += __shfl_xor_sync(0xffffffffu, rsum, 2);
            if (tig == 0) spart[lr * 2 + wn] = rsum;
        }
    }
    __syncthreads();
    if (tid < 128) {
        float ps = spart[tid * 2] + spart[tid * 2 + 1];
        g_psum[((size_t)bh * Sdim + q0 + tid) * 16 + kt] = ps;
    }
}

// ---------------------------------------------------------------------------
// K2b: inv = 1 / sum(16 partials)
// ---------------------------------------------------------------------------
__global__ void __launch_bounds__(256) rowsum_inv_kernel()
{
    int idx = blockIdx.x * 256 + threadIdx.x;
    const float* p = g_psum + (size_t)idx * 16;
    float s = 0.f;
#pragma unroll
    for (int i = 0; i < 16; i++) s += p[i];
    g_inv[idx] = 1.0f / s;
}

// ---------------------------------------------------------------------------
// K3: head-mean (pure stream) from single fp16 plane
// ---------------------------------------------------------------------------
__global__ void __launch_bounds__(256) mean_kernel(float* __restrict__ mean_out)
{
    const int bq = blockIdx.x;
    const int b = bq >> 11, q = bq & 2047;
    const int tid = threadIdx.x;
    const int pbase = tid * 4;

    __shared__ float inv_s[8];
    if (tid < 8) inv_s[tid] = g_inv[(size_t)(b * NH + tid) * Sdim + q];
    __syncthreads();

    float macc[8];
#pragma unroll
    for (int j = 0; j < 8; j++) macc[j] = 0.f;

#pragma unroll
    for (int h = 0; h < NH; h++) {
        size_t rb = ((size_t)((b * NH + h) * Sdim + q)) * (Sdim / 2);
        uint4 vw = *(const uint4*)&g_e[rb + pbase];
        uint32_t w[4] = {vw.x, vw.y, vw.z, vw.w};
        float invh = inv_s[h];
#pragma unroll
        for (int m = 0; m < 4; m++) {
            __half2 hp = *(__half2*)&w[m];
            float2 f = __half22float2(hp);
            macc[2 * m]     = fmaf(f.x, invh, macc[2 * m]);
            macc[2 * m + 1] = fmaf(f.y, invh, macc[2 * m + 1]);
        }
    }

    float* mrow = mean_out + ((size_t)(b * Sdim + q)) * Sdim + tid * 8;
    float4 m0 = {macc[0] * 0.125f, macc[1] * 0.125f, macc[2] * 0.125f, macc[3] * 0.125f};
    float4 m1 = {macc[4] * 0.125f, macc[5] * 0.125f, macc[6] * 0.125f, macc[7] * 0.125f};
    *(float4*)&mrow[0] = m0;
    *(float4*)&mrow[4] = m1;
}

// ---------------------------------------------------------------------------
// K4: pv via plain fp16 1-term mma: ctx = inv * (e @ V).
// Stage (24KB): W +0 (16KB) | V +16384 (8KB). 2 stages.
// ---------------------------------------------------------------------------
#define PV_STAGE_B 24576
#define PV_V_OFF   16384
#define PV_BASE    1024
#define PV_SMEM_B  (PV_BASE + 2 * PV_STAGE_B)   // 50176

__global__ void __launch_bounds__(256, 2) pv_mma_kernel()
{
    extern __shared__ __align__(16) char sm[];
    float* inv_s = (float*)sm;

    const int tid = threadIdx.x, lane = tid & 31, wid = tid >> 5;
    const int bh = blockIdx.y, b = bh >> 3, h = bh & 7;
    const int q0 = blockIdx.x * 128;

    const uint32_t* Ep = g_e + ((size_t)bh * Sdim + q0) * (Sdim / 2);
    const __half* V_src = g_v + (size_t)b * Sdim * Hdim + h * HD;

    const uint32_t sb = smem_u32(sm);
    const int wm = wid & 3, wn = wid >> 2;

    if (tid < 128)
        inv_s[tid] = g_inv[(size_t)bh * Sdim + q0 + tid];

    float d[2][4][4];
#pragma unroll
    for (int mt = 0; mt < 2; mt++)
#pragma unroll
        for (int nt = 0; nt < 4; nt++)
#pragma unroll
            for (int e = 0; e < 4; e++) d[mt][nt][e] = 0.f;

#define PV_CPW(kc, st)                                                            \
    _Pragma("unroll") for (int i = 0; i < 4; i++) {                               \
        int idx = tid + 256 * i; int r = idx >> 3, cc = idx & 7;                  \
        uint32_t soff = r * 128 + ((cc * 16) ^ ((r & 7) * 16));                   \
        uint32_t base = sb + PV_BASE + (st) * PV_STAGE_B;                         \
        size_t go = (size_t)r * (Sdim / 2) + ((kc) >> 1) + cc * 4;                \
        cp_async16(base + soff, &Ep[go]);                                         \
    }

#define PV_CPV(kc, st)                                                            \
    _Pragma("unroll") for (int i = 0; i < 2; i++) {                               \
        int idx = tid + 256 * i; int kk = idx >> 3, c8 = idx & 7;                 \
        uint32_t soff = kk * 128 + ((c8 * 16) ^ ((kk & 7) * 16));                 \
        uint32_t base = sb + PV_BASE + (st) * PV_STAGE_B;                         \
        cp_async16(base + PV_V_OFF + soff, &V_src[(size_t)((kc) + kk) * Hdim + c8 * 8]); \
    }

    PV_CPW(0, 0)
    PV_CPV(0, 0)
    CP_COMMIT();
    CP_WAIT0();
    __syncthreads();

    for (int c = 0; c < 32; c++) {
        const int st = c & 1;
        if (c < 31) {
            PV_CPW((c + 1) * 64, st ^ 1)
            PV_CPV((c + 1) * 64, st ^ 1)
            CP_COMMIT();
        }
        {
            const uint32_t wbase = sb + PV_BASE + st * PV_STAGE_B;
            const uint32_t vbase = wbase + PV_V_OFF;
#pragma unroll
            for (int ks = 0; ks < 4; ks++) {
                uint32_t aw[2][4];
#pragma unroll
                for (int mt = 0; mt < 2; mt++) {
                    int row = wm * 32 + mt * 16 + (lane & 15);
                    uint32_t colb = (ks * 16 + (lane >> 4) * 8) * 2;
                    uint32_t adr = wbase + row * 128 + (colb ^ ((row & 7) * 16));
                    ldsm_x4(aw[mt], adr);
                }
                uint32_t bhf[4][2];
#pragma unroll
                for (int nt = 0; nt < 4; nt++) {
                    int rowk = ks * 16 + (lane & 15);
                    uint32_t colb = (wn * 32 + nt * 8) * 2;
                    uint32_t adr = vbase + rowk * 128 + (colb ^ ((rowk & 7) * 16));
                    ldsm_x2t(bhf[nt], adr);
                }
#pragma unroll
                for (int mt = 0; mt < 2; mt++)
#pragma unroll
                    for (int nt = 0; nt < 4; nt++)
                        mma_f16(d[mt][nt], aw[mt], bhf[nt]);
            }
        }
        if (c < 31) { CP_WAIT0(); }
        __syncthreads();
    }

    const int g = lane >> 2, tig = lane & 3;
#pragma unroll
    for (int mt = 0; mt < 2; mt++)
#pragma unroll
        for (int nt = 0; nt < 4; nt++)
#pragma unroll
            for (int hf = 0; hf < 2; hf++) {
                int lr = wm * 32 + mt * 16 + g + hf * 8;
                float inv = inv_s[lr];
                int m = q0 + lr;
                int col = h * HD + wn * 32 + nt * 8 + tig * 2;
                float e0 = d[mt][nt][hf * 2 + 0] * inv;
                float e1 = d[mt][nt][hf * 2 + 1] * inv;
                size_t off = (size_t)(b * Sdim + m) * Hdim + col;
                *(uint32_t*)&g_ctx[off] = pack_f16x2(e0, e1);
            }
}

// ---------------------------------------------------------------------------
extern "C" void kernel_launch(void* const* d_in, const int* in_sizes, int n_in,
                              void* d_out, int out_size)
{
    const float* x     = (const float*)d_in[0];
    const float* pos   = (const float*)d_in[1];
    const int*   mask  = (const int*)d_in[2];
    const float* w_qkv = (const float*)d_in[3];
    const float* b_qkv = (const float*)d_in[4];
    const float* w_out = (const float*)d_in[5];
    const float* b_out = (const float*)d_in[6];

    float* out_proj = (float*)d_out;
    float* mean_out = out_proj + (size_t)Bdim * Sdim * Hdim;

    __half *p_x, *p_wq, *p_wo, *p_c;
    cudaGetSymbolAddress((void**)&p_x, g_x);
    cudaGetSymbolAddress((void**)&p_wq, g_wqkv);
    cudaGetSymbolAddress((void**)&p_wo, g_wout);
    cudaGetSymbolAddress((void**)&p_c, g_ctx);

    static cudaStream_t s_side = nullptr;
    static cudaEvent_t ev_fork = nullptr, ev_join = nullptr;
    if (!s_side) {
        int prio_lo = 0, prio_hi = 0;
        cudaDeviceGetStreamPriorityRange(&prio_lo, &prio_hi);
        cudaStreamCreateWithPriority(&s_side, cudaStreamNonBlocking, prio_lo);
        cudaEventCreateWithFlags(&ev_fork, cudaEventDisableTiming);
        cudaEventCreateWithFlags(&ev_join, cudaEventDisableTiming);
        cudaFuncSetAttribute(gemm512_mma_kernel<0>, cudaFuncAttributeMaxDynamicSharedMemorySize, GQ_SMEM);
        cudaFuncSetAttribute(gemm512_mma_kernel<1>, cudaFuncAttributeMaxDynamicSharedMemorySize, GQ_SMEM);
        cudaFuncSetAttribute(scores_mma_kernel, cudaFuncAttributeMaxDynamicSharedMemorySize, SC_SMEM);
        cudaFuncSetAttribute(pv_mma_kernel, cudaFuncAttributeMaxDynamicSharedMemorySize, PV_SMEM_B);
    }

    // K0: convert inputs to fp16
    conv4_f16_kernel<<<(Bdim * Sdim * Hdim / 4 + 255) / 256, 256>>>(x, p_x, Bdim * Sdim * Hdim / 4);
    conv4_f16_kernel<<<(H3 * Hdim / 4 + 255) / 256, 256>>>(w_qkv, p_wq, H3 * Hdim / 4);
    conv4_f16_kernel<<<(Hdim * Hdim / 4 + 255) / 256, 256>>>(w_out, p_wo, Hdim * Hdim / 4);

    // K1: QKV projection (fp16 1-term) + scatter
    {
        dim3 grid(H3 / 128, (Bdim * Sdim) / 128);
        gemm512_mma_kernel<0><<<grid, 256, GQ_SMEM>>>(p_x, p_wq, b_qkv, nullptr, H3);
    }
    // K2: scores (fp16 1-term) -> exp fp16 plane + partial sums
    {
        dim3 grid(Sdim / 128, Sdim / 128, Bdim * NH);
        scores_mma_kernel<<<grid, 256, SC_SMEM>>>(pos, mask);
    }
    // K2b: row inverse sums
    rowsum_inv_kernel<<<(Bdim * NH * Sdim) / 256, 256>>>();

    // fork: pv (main, priority) ∥ mean (side, low priority)
    cudaEventRecord(ev_fork, 0);
    cudaStreamWaitEvent(s_side, ev_fork, 0);

    {
        dim3 grid(Sdim / 128, Bdim * NH);
        pv_mma_kernel<<<grid, 256, PV_SMEM_B>>>();
    }
    mean_kernel<<<Bdim * Sdim, 256, 0, s_side>>>(mean_out);
    cudaEventRecord(ev_join, s_side);

    // K5: output projection (fp16 1-term)
    {
        dim3 grid(Hdim / 128, (Bdim * Sdim) / 128);
        gemm512_mma_kernel<1><<<grid, 256, GQ_SMEM>>>(p_c, p_wo, b_out, out_proj, Hdim);
    }
    // join
    cudaStreamWaitEvent(0, ev_join, 0);
}

// round 17
// speedup vs baseline: 2.5098x; 1.3902x over previous
#include <cuda_runtime.h>
#include <cuda_fp16.h>
#include <math.h>
#include <stdint.h>

#define Bdim 4
#define Sdim 2048
#define Hdim 512
#define NH   8
#define HD   64
#define H3   1536

// Static scratch (allocation-guard-safe)
__device__ uint32_t g_e[(size_t)Bdim * NH * Sdim * Sdim / 2];   // fp16 pairs: exp(score), COMPACTED key axis
__device__ float g_psum[(size_t)Bdim * NH * Sdim * 16];
__device__ float g_inv[(size_t)Bdim * NH * Sdim];
__device__ int   g_kidx[Bdim][Sdim];
__device__ int   g_nvalid[Bdim];
__device__ __half g_q[(size_t)Bdim * NH * Sdim * HD];
__device__ __half g_k[(size_t)Bdim * NH * Sdim * HD];
__device__ __half g_v[(size_t)Bdim * Sdim * Hdim];
__device__ __half g_x[(size_t)Bdim * Sdim * Hdim];
__device__ __half g_wqkv[(size_t)H3 * Hdim];
__device__ __half g_wout[(size_t)Hdim * Hdim];
__device__ __half g_ctx[(size_t)Bdim * Sdim * Hdim];

// ---- helpers ----------------------------------------------------------------
__device__ __forceinline__ uint32_t smem_u32(const void* p) {
    uint32_t a;
    asm("{ .reg .u64 t; cvta.to.shared.u64 t, %1; cvt.u32.u64 %0, t; }" : "=r"(a) : "l"(p));
    return a;
}
__device__ __forceinline__ void ldsm_x4(uint32_t* r, uint32_t addr) {
    asm volatile("ldmatrix.sync.aligned.m8n8.x4.shared.b16 {%0,%1,%2,%3}, [%4];"
                 : "=r"(r[0]), "=r"(r[1]), "=r"(r[2]), "=r"(r[3]) : "r"(addr));
}
__device__ __forceinline__ void ldsm_x2(uint32_t* r, uint32_t addr) {
    asm volatile("ldmatrix.sync.aligned.m8n8.x2.shared.b16 {%0,%1}, [%2];"
                 : "=r"(r[0]), "=r"(r[1]) : "r"(addr));
}
__device__ __forceinline__ void ldsm_x2t(uint32_t* r, uint32_t addr) {
    asm volatile("ldmatrix.sync.aligned.m8n8.x2.trans.shared.b16 {%0,%1}, [%2];"
                 : "=r"(r[0]), "=r"(r[1]) : "r"(addr));
}
__device__ __forceinline__ void mma_f16(float* d, const uint32_t* a, const uint32_t* b) {
    asm volatile("mma.sync.aligned.m16n8k16.row.col.f32.f16.f16.f32 "
                 "{%0,%1,%2,%3}, {%4,%5,%6,%7}, {%8,%9}, {%0,%1,%2,%3};"
                 : "+f"(d[0]), "+f"(d[1]), "+f"(d[2]), "+f"(d[3])
                 : "r"(a[0]), "r"(a[1]), "r"(a[2]), "r"(a[3]), "r"(b[0]), "r"(b[1]));
}
__device__ __forceinline__ uint32_t pack_f16x2(float a, float b) {
    __half2 h = __floats2half2_rn(a, b);
    return *(uint32_t*)&h;
}
__device__ __forceinline__ void cp_async16(uint32_t saddr, const void* gptr) {
    asm volatile("cp.async.cg.shared.global [%0], [%1], 16;" :: "r"(saddr), "l"(gptr));
}
#define CP_COMMIT() asm volatile("cp.async.commit_group;")
#define CP_WAIT0()  asm volatile("cp.async.wait_group 0;")

// ---------------------------------------------------------------------------
// K0: convert fp32 -> single fp16 plane
// ---------------------------------------------------------------------------
__global__ void __launch_bounds__(256) conv4_f16_kernel(
    const float* __restrict__ src, __half* __restrict__ dst, int n4)
{
    int i = blockIdx.x * 256 + threadIdx.x;
    if (i >= n4) return;
    float4 v = ((const float4*)src)[i];
    ((uint2*)dst)[i] = make_uint2(pack_f16x2(v.x, v.y), pack_f16x2(v.z, v.w));
}

// ---------------------------------------------------------------------------
// K0m: mask scan -> compacted valid-key index list per batch (deterministic)
// ---------------------------------------------------------------------------
__global__ void __launch_bounds__(256) mask_scan_kernel(const int* __restrict__ mask)
{
    const int b = blockIdx.x, tid = threadIdx.x;
    const int lane = tid & 31, wid = tid >> 5;
    __shared__ int wsum[8];

    int m[8], c = 0;
#pragma unroll
    for (int i = 0; i < 8; i++) {
        m[i] = (mask[b * Sdim + tid * 8 + i] != 0);
        c += m[i];
    }
    int sc = c;
#pragma unroll
    for (int o = 1; o < 32; o <<= 1) {
        int v = __shfl_up_sync(0xffffffffu, sc, o);
        if (lane >= o) sc += v;
    }
    if (lane == 31) wsum[wid] = sc;
    __syncthreads();
    int woff = 0;
#pragma unroll
    for (int w = 0; w < 8; w++) woff += (w < wid) ? wsum[w] : 0;
    int off = woff + sc - c;
#pragma unroll
    for (int i = 0; i < 8; i++)
        if (m[i]) g_kidx[b][off++] = tid * 8 + i;
    if (tid == 255) g_nvalid[b] = woff + sc;
}

// ---------------------------------------------------------------------------
// K1/K5: plain fp16 1-term mma.sync GEMM, K=512 (unchanged from round 16)
// ---------------------------------------------------------------------------
#define GQ_STAGE 16384
#define GQ_SMEM (2 * GQ_STAGE + 512)

template<int MODE>
__global__ void __launch_bounds__(256, 2) gemm512_mma_kernel(
    const __half* __restrict__ A, const __half* __restrict__ B,
    const float* __restrict__ bias, float* __restrict__ Cout, int Ncols)
{
    extern __shared__ __align__(16) char sm[];
    float* bias_s = (float*)(sm + 2 * GQ_STAGE);

    const int tid = threadIdx.x, lane = tid & 31, wid = tid >> 5;
    const int m0 = blockIdx.y * 128, n0 = blockIdx.x * 128;
    const int wm = wid & 3, wn = wid >> 2;
    const uint32_t sb = smem_u32(sm);

    if (tid < 128) bias_s[tid] = bias[n0 + tid];

    float d[2][8][4];
#pragma unroll
    for (int mt = 0; mt < 2; mt++)
#pragma unroll
        for (int nt = 0; nt < 8; nt++)
#pragma unroll
            for (int e = 0; e < 4; e++) d[mt][nt][e] = 0.f;

#define GQ_CP(kc, st)                                                             \
    _Pragma("unroll") for (int i = 0; i < 2; i++) {                               \
        int idx = tid + 256 * i; int r = idx >> 2, cc = idx & 3;                  \
        uint32_t so = (uint32_t)(st) * GQ_STAGE + r * 64 +                        \
                      ((uint32_t)(cc ^ ((r >> 1) & 3)) << 4);                     \
        size_t ga = (size_t)(m0 + r) * 512 + (kc) + cc * 8;                       \
        size_t gb = (size_t)(n0 + r) * 512 + (kc) + cc * 8;                       \
        cp_async16(sb + so,        &A[ga]);                                       \
        cp_async16(sb + so + 8192, &B[gb]);                                       \
    }                                                                             \
    CP_COMMIT();

    GQ_CP(0, 0)
    CP_WAIT0();
    __syncthreads();

    for (int c = 0; c < 16; c++) {
        const int st = c & 1;
        if (c < 15) { GQ_CP((c + 1) * 32, st ^ 1) }
        const uint32_t abase = sb + st * GQ_STAGE;
        const uint32_t bbase = abase + 8192;
#pragma unroll
        for (int ks = 0; ks < 2; ks++) {
            uint32_t ah[2][4];
#pragma unroll
            for (int mt = 0; mt < 2; mt++) {
                int row = wm * 32 + mt * 16 + (lane & 15);
                int c16 = ks * 2 + (lane >> 4);
                uint32_t adr = abase + row * 64 + ((uint32_t)(c16 ^ ((row >> 1) & 3)) << 4);
                ldsm_x4(ah[mt], adr);
            }
            uint32_t bhf[8][2];
#pragma unroll
            for (int p = 0; p < 4; p++) {
                int i4 = lane >> 3;
                int row = wn * 64 + p * 16 + (i4 & 1) * 8 + (lane & 7);
                int c16 = ks * 2 + (i4 >> 1);
                uint32_t adr = bbase + row * 64 + ((uint32_t)(c16 ^ ((row >> 1) & 3)) << 4);
                uint32_t t[4];
                ldsm_x4(t, adr);
                bhf[2 * p][0] = t[0]; bhf[2 * p][1] = t[2];
                bhf[2 * p + 1][0] = t[1]; bhf[2 * p + 1][1] = t[3];
            }
#pragma unroll
            for (int mt = 0; mt < 2; mt++)
#pragma unroll
                for (int nt = 0; nt < 8; nt++)
                    mma_f16(d[mt][nt], ah[mt], bhf[nt]);
        }
        if (c < 15) { CP_WAIT0(); }
        __syncthreads();
    }

    const int g = lane >> 2, tig = lane & 3;
#pragma unroll
    for (int mt = 0; mt < 2; mt++) {
#pragma unroll
        for (int hf = 0; hf < 2; hf++) {
            int m = m0 + wm * 32 + mt * 16 + hf * 8 + g;
            if (MODE == 0) {
                int b = m >> 11, s = m & 2047;
#pragma unroll
                for (int nt = 0; nt < 8; nt++) {
                    int cl = wn * 64 + nt * 8 + tig * 2;
                    int col = n0 + cl;
                    float e0 = d[mt][nt][hf * 2 + 0] + bias_s[cl];
                    float e1 = d[mt][nt][hf * 2 + 1] + bias_s[cl + 1];
                    uint32_t p01 = pack_f16x2(e0, e1);
                    int region = col >> 9;
                    if (region < 2) {
                        int head = (col >> 6) & 7;
                        int d0 = col & 63;
                        size_t off = ((size_t)(b * NH + head) * Sdim + s) * HD + d0;
                        if (region == 0) *(uint32_t*)&g_q[off] = p01;
                        else             *(uint32_t*)&g_k[off] = p01;
                    } else {
                        size_t off = ((size_t)b * Sdim + s) * Hdim + (col - 1024);
                        *(uint32_t*)&g_v[off] = p01;
                    }
                }
            } else {
                float* crow = Cout + (size_t)m * Ncols;
#pragma unroll
                for (int nt = 0; nt < 8; nt++) {
                    int cl = wn * 64 + nt * 8 + tig * 2;
                    float2 o = {d[mt][nt][hf * 2 + 0] + bias_s[cl],
                                d[mt][nt][hf * 2 + 1] + bias_s[cl + 1]};
                    *(float2*)&crow[n0 + cl] = o;
                }
            }
        }
    }
}

// ---------------------------------------------------------------------------
// K2: scores on COMPACTED key axis. K rows gathered via kidx; tail padded e=0.
// ---------------------------------------------------------------------------
#define SQS 72
#define SC_ARR (128 * SQS)
#define SC_SMEM (2 * SC_ARR * 2 + 2 * 128 * 16 + 128 * 2 * 4)
#define CLOG2E 0.1803368801111137f   // 0.125 * log2(e)

__global__ void __launch_bounds__(256, 2) scores_mma_kernel(
    const float* __restrict__ pos)
{
    extern __shared__ __align__(16) char sm[];
    __half* Qs = (__half*)sm;
    float4* Pq4 = (float4*)(sm + 2 * SC_ARR * 2);
    float4* Pk4 = Pq4 + 128;
    float* spart = (float*)(Pk4 + 128);

    const int tid = threadIdx.x, lane = tid & 31, wid = tid >> 5;
    const int bh = blockIdx.z, b = bh >> 3;
    const int q0 = blockIdx.y * 128, k0 = blockIdx.x * 128;
    const int kt = blockIdx.x;

    const int nv = g_nvalid[b];
    if (k0 >= nv) return;   // inactive tile; rowsum skips its psum slot

    const __half* sQ = g_q + ((size_t)bh * Sdim + q0) * HD;
    const __half* sKb = g_k + (size_t)bh * Sdim * HD;

    const uint32_t qb = smem_u32(Qs);
#pragma unroll
    for (int i = 0; i < 4; i++) {
        int idx = tid + 256 * i;
        int r = idx >> 3, c = idx & 7;
        uint32_t so = (r * SQS + c * 8) * 2;
        cp_async16(qb + so, &sQ[(size_t)r * HD + c * 8]);
        int j = k0 + r;
        int sidx = (j < nv) ? g_kidx[b][j] : 0;
        cp_async16(qb + so + SC_ARR * 2, &sKb[(size_t)sidx * HD + c * 8]);
    }
    CP_COMMIT();

    if (tid < 128) {
        const float* pp = &pos[(size_t)(b * Sdim + q0 + tid) * 3];
        Pq4[tid] = make_float4(pp[0], pp[1], pp[2], 0.f);
    } else {
        int t2 = tid - 128;
        int j = k0 + t2;
        int valid = (j < nv);
        int sidx = valid ? g_kidx[b][j] : 0;
        const float* pp = &pos[(size_t)(b * Sdim + sidx) * 3];
        Pk4[t2] = make_float4(pp[0], pp[1], pp[2], valid ? 1.f : 0.f);
    }
    CP_WAIT0();
    __syncthreads();

    const int wm = wid & 3, wn = wid >> 2;
    const uint32_t kb = qb + SC_ARR * 2;

    float d[2][8][4];
#pragma unroll
    for (int mt = 0; mt < 2; mt++)
#pragma unroll
        for (int nt = 0; nt < 8; nt++)
#pragma unroll
            for (int e = 0; e < 4; e++) d[mt][nt][e] = 0.f;

#pragma unroll
    for (int ks = 0; ks < 4; ks++) {
        uint32_t ah[2][4];
#pragma unroll
        for (int mt = 0; mt < 2; mt++) {
            int row = wm * 32 + mt * 16 + (lane & 15);
            int col = ks * 16 + (lane >> 4) * 8;
            uint32_t adr = qb + (row * SQS + col) * 2;
            ldsm_x4(ah[mt], adr);
        }
        uint32_t bhf[8][2];
#pragma unroll
        for (int nt = 0; nt < 8; nt++) {
            int row = wn * 64 + nt * 8 + (lane & 7);
            int col = ks * 16 + ((lane >> 3) & 1) * 8;
            uint32_t adr = kb + (row * SQS + col) * 2;
            ldsm_x2(bhf[nt], adr);
        }
#pragma unroll
        for (int mt = 0; mt < 2; mt++)
#pragma unroll
            for (int nt = 0; nt < 8; nt++)
                mma_f16(d[mt][nt], ah[mt], bhf[nt]);
    }

    const int g = lane >> 2, tig = lane & 3;
#pragma unroll
    for (int mt = 0; mt < 2; mt++) {
#pragma unroll
        for (int hf = 0; hf < 2; hf++) {
            int lr = wm * 32 + mt * 16 + hf * 8 + g;
            float4 pq = Pq4[lr];
            uint32_t* erow = g_e + ((size_t)bh * Sdim + q0 + lr) * (Sdim / 2) + (k0 >> 1);
            float rsum = 0.f;
#pragma unroll
            for (int nt = 0; nt < 8; nt++) {
                int lc = wn * 64 + nt * 8 + tig * 2;
                float4 pk0 = Pk4[lc];
                float4 pk1 = Pk4[lc + 1];
                float v0 = d[mt][nt][hf * 2 + 0];
                float v1 = d[mt][nt][hf * 2 + 1];
                float dx0 = pq.x - pk0.x, dy0 = pq.y - pk0.y, dz0 = pq.z - pk0.z;
                float dx1 = pq.x - pk1.x, dy1 = pq.y - pk1.y, dz1 = pq.z - pk1.z;
                float s0 = (v0 - (dx0 * dx0 + dy0 * dy0 + dz0 * dz0)) * CLOG2E;
                float s1 = (v1 - (dx1 * dx1 + dy1 * dy1 + dz1 * dz1)) * CLOG2E;
                float e0 = exp2f(s0) * pk0.w;
                float e1 = exp2f(s1) * pk1.w;
                __half hh0 = __float2half_rn(e0);
                __half hh1 = __float2half_rn(e1);
                rsum += __half2float(hh0) + __half2float(hh1);
                erow[lc >> 1] = ((uint32_t)__half_as_ushort(hh1) << 16) | __half_as_ushort(hh0);
            }
            rsum += __shfl_xor_sync(0xffffffffu, rsum, 1);
            rsum += __shfl_xor_sync(0xffffffffu, rsum, 2);
            if (tig == 0) spart[lr * 2 + wn] = rsum;
        }
    }
    __syncthreads();
    if (tid < 128) {
        float ps = spart[tid * 2] + spart[tid * 2 + 1];
        g_psum[((size_t)bh * Sdim + q0 + tid) * 16 + kt] = ps;
    }
}

// ---------------------------------------------------------------------------
// K2b: inv = 1 / sum over ACTIVE tiles only
// ---------------------------------------------------------------------------
__global__ void __launch_bounds__(256) rowsum_inv_kernel()
{
    int idx = blockIdx.x * 256 + threadIdx.x;
    int b = idx >> 14;   // NH * Sdim = 16384
    int nt = (g_nvalid[b] + 127) >> 7;
    const float* p = g_psum + (size_t)idx * 16;
    float s = 0.f;
    for (int i = 0; i < nt; i++) s += p[i];
    g_inv[idx] = 1.0f / s;
}

// ---------------------------------------------------------------------------
// K3: head-mean: zero-fill full row, then scatter compacted contributions.
// Block = one (b,q) row.
// ---------------------------------------------------------------------------
__global__ void __launch_bounds__(256) mean_kernel(float* __restrict__ mean_out)
{
    const int bq = blockIdx.x;
    const int b = bq >> 11, q = bq & 2047;
    const int tid = threadIdx.x;

    __shared__ float inv_s[8];
    if (tid < 8) inv_s[tid] = g_inv[(size_t)(b * NH + tid) * Sdim + q];

    float* mrow = mean_out + ((size_t)(b * Sdim + q)) * Sdim;
    // phase 1: zero-fill (masked outputs are exactly 0)
    float4 z = {0.f, 0.f, 0.f, 0.f};
    *(float4*)&mrow[tid * 8]     = z;
    *(float4*)&mrow[tid * 8 + 4] = z;
    __syncthreads();

    // phase 2: scatter valid contributions from compacted e
    const int nv = g_nvalid[b];
    const int j0 = tid * 8;
    if (j0 >= nv) return;

    float macc[8];
#pragma unroll
    for (int j = 0; j < 8; j++) macc[j] = 0.f;

#pragma unroll
    for (int h = 0; h < NH; h++) {
        size_t rb = ((size_t)((b * NH + h) * Sdim + q)) * (Sdim / 2);
        uint4 vw = *(const uint4*)&g_e[rb + (j0 >> 1)];
        uint32_t w[4] = {vw.x, vw.y, vw.z, vw.w};
        float invh = inv_s[h];
#pragma unroll
        for (int m = 0; m < 4; m++) {
            __half2 hp = *(__half2*)&w[m];
            float2 f = __half22float2(hp);
            macc[2 * m]     = fmaf(f.x, invh, macc[2 * m]);
            macc[2 * m + 1] = fmaf(f.y, invh, macc[2 * m + 1]);
        }
    }
#pragma unroll
    for (int j = 0; j < 8; j++) {
        if (j0 + j < nv) {
            int k = g_kidx[b][j0 + j];
            mrow[k] = macc[j] * 0.125f;
        }
    }
}

// ---------------------------------------------------------------------------
// K4: pv on COMPACTED key axis: ctx = inv * (e_c @ V_gathered).
// ---------------------------------------------------------------------------
#define PV_STAGE_B 24576
#define PV_V_OFF   16384
#define PV_BASE    1024
#define PV_SMEM_B  (PV_BASE + 2 * PV_STAGE_B)   // 50176

__global__ void __launch_bounds__(256, 2) pv_mma_kernel()
{
    extern __shared__ __align__(16) char sm[];
    float* inv_s = (float*)sm;

    const int tid = threadIdx.x, lane = tid & 31, wid = tid >> 5;
    const int bh = blockIdx.y, b = bh >> 3, h = bh & 7;
    const int q0 = blockIdx.x * 128;

    const uint32_t* Ep = g_e + ((size_t)bh * Sdim + q0) * (Sdim / 2);
    const __half* Vb = g_v + (size_t)b * Sdim * Hdim + h * HD;

    const uint32_t sb = smem_u32(sm);
    const int wm = wid & 3, wn = wid >> 2;
    const int nv = g_nvalid[b];
    const int nch = (nv + 63) >> 6;

    if (tid < 128)
        inv_s[tid] = g_inv[(size_t)bh * Sdim + q0 + tid];

    float d[2][4][4];
#pragma unroll
    for (int mt = 0; mt < 2; mt++)
#pragma unroll
        for (int nt = 0; nt < 4; nt++)
#pragma unroll
            for (int e = 0; e < 4; e++) d[mt][nt][e] = 0.f;

#define PV_CPW(kc, st)                                                            \
    _Pragma("unroll") for (int i = 0; i < 4; i++) {                               \
        int idx = tid + 256 * i; int r = idx >> 3, cc = idx & 7;                  \
        uint32_t soff = r * 128 + ((cc * 16) ^ ((r & 7) * 16));                   \
        uint32_t base = sb + PV_BASE + (st) * PV_STAGE_B;                         \
        size_t go = (size_t)r * (Sdim / 2) + ((kc) >> 1) + cc * 4;                \
        cp_async16(base + soff, &Ep[go]);                                         \
    }

#define PV_CPV(kc, st)                                                            \
    _Pragma("unroll") for (int i = 0; i < 2; i++) {                               \
        int idx = tid + 256 * i; int kk = idx >> 3, c8 = idx & 7;                 \
        int j = (kc) + kk;                                                        \
        int sidx = (j < nv) ? g_kidx[b][j] : 0;                                   \
        uint32_t soff = kk * 128 + ((c8 * 16) ^ ((kk & 7) * 16));                 \
        uint32_t base = sb + PV_BASE + (st) * PV_STAGE_B;                         \
        cp_async16(base + PV_V_OFF + soff, &Vb[(size_t)sidx * Hdim + c8 * 8]);    \
    }

    PV_CPW(0, 0)
    PV_CPV(0, 0)
    CP_COMMIT();
    CP_WAIT0();
    __syncthreads();

    for (int c = 0; c < nch; c++) {
        const int st = c & 1;
        if (c + 1 < nch) {
            PV_CPW((c + 1) * 64, st ^ 1)
            PV_CPV((c + 1) * 64, st ^ 1)
            CP_COMMIT();
        }
        {
            const uint32_t wbase = sb + PV_BASE + st * PV_STAGE_B;
            const uint32_t vbase = wbase + PV_V_OFF;
#pragma unroll
            for (int ks = 0; ks < 4; ks++) {
                uint32_t aw[2][4];
#pragma unroll
                for (int mt = 0; mt < 2; mt++) {
                    int row = wm * 32 + mt * 16 + (lane & 15);
                    uint32_t colb = (ks * 16 + (lane >> 4) * 8) * 2;
                    uint32_t adr = wbase + row * 128 + (colb ^ ((row & 7) * 16));
                    ldsm_x4(aw[mt], adr);
                }
                uint32_t bhf[4][2];
#pragma unroll
                for (int nt = 0; nt < 4; nt++) {
                    int rowk = ks * 16 + (lane & 15);
                    uint32_t colb = (wn * 32 + nt * 8) * 2;
                    uint32_t adr = vbase + rowk * 128 + (colb ^ ((rowk & 7) * 16));
                    ldsm_x2t(bhf[nt], adr);
                }
#pragma unroll
                for (int mt = 0; mt < 2; mt++)
#pragma unroll
                    for (int nt = 0; nt < 4; nt++)
                        mma_f16(d[mt][nt], aw[mt], bhf[nt]);
            }
        }
        if (c + 1 < nch) { CP_WAIT0(); }
        __syncthreads();
    }

    const int g = lane >> 2, tig = lane & 3;
#pragma unroll
    for (int mt = 0; mt < 2; mt++)
#pragma unroll
        for (int nt = 0; nt < 4; nt++)
#pragma unroll
            for (int hf = 0; hf < 2; hf++) {
                int lr = wm * 32 + mt * 16 + g + hf * 8;
                float inv = inv_s[lr];
                int m = q0 + lr;
                int col = h * HD + wn * 32 + nt * 8 + tig * 2;
                float e0 = d[mt][nt][hf * 2 + 0] * inv;
                float e1 = d[mt][nt][hf * 2 + 1] * inv;
                size_t off = (size_t)(b * Sdim + m) * Hdim + col;
                *(uint32_t*)&g_ctx[off] = pack_f16x2(e0, e1);
            }
}

// ---------------------------------------------------------------------------
extern "C" void kernel_launch(void* const* d_in, const int* in_sizes, int n_in,
                              void* d_out, int out_size)
{
    const float* x     = (const float*)d_in[0];
    const float* pos   = (const float*)d_in[1];
    const int*   mask  = (const int*)d_in[2];
    const float* w_qkv = (const float*)d_in[3];
    const float* b_qkv = (const float*)d_in[4];
    const float* w_out = (const float*)d_in[5];
    const float* b_out = (const float*)d_in[6];

    float* out_proj = (float*)d_out;
    float* mean_out = out_proj + (size_t)Bdim * Sdim * Hdim;

    __half *p_x, *p_wq, *p_wo, *p_c;
    cudaGetSymbolAddress((void**)&p_x, g_x);
    cudaGetSymbolAddress((void**)&p_wq, g_wqkv);
    cudaGetSymbolAddress((void**)&p_wo, g_wout);
    cudaGetSymbolAddress((void**)&p_c, g_ctx);

    static cudaStream_t s_side = nullptr;
    static cudaEvent_t ev_fork = nullptr, ev_join = nullptr;
    if (!s_side) {
        int prio_lo = 0, prio_hi = 0;
        cudaDeviceGetStreamPriorityRange(&prio_lo, &prio_hi);
        cudaStreamCreateWithPriority(&s_side, cudaStreamNonBlocking, prio_lo);
        cudaEventCreateWithFlags(&ev_fork, cudaEventDisableTiming);
        cudaEventCreateWithFlags(&ev_join, cudaEventDisableTiming);
        cudaFuncSetAttribute(gemm512_mma_kernel<0>, cudaFuncAttributeMaxDynamicSharedMemorySize, GQ_SMEM);
        cudaFuncSetAttribute(gemm512_mma_kernel<1>, cudaFuncAttributeMaxDynamicSharedMemorySize, GQ_SMEM);
        cudaFuncSetAttribute(scores_mma_kernel, cudaFuncAttributeMaxDynamicSharedMemorySize, SC_SMEM);
        cudaFuncSetAttribute(pv_mma_kernel, cudaFuncAttributeMaxDynamicSharedMemorySize, PV_SMEM_B);
    }

    // K0: convert inputs + mask scan
    conv4_f16_kernel<<<(Bdim * Sdim * Hdim / 4 + 255) / 256, 256>>>(x, p_x, Bdim * Sdim * Hdim / 4);
    conv4_f16_kernel<<<(H3 * Hdim / 4 + 255) / 256, 256>>>(w_qkv, p_wq, H3 * Hdim / 4);
    conv4_f16_kernel<<<(Hdim * Hdim / 4 + 255) / 256, 256>>>(w_out, p_wo, Hdim * Hdim / 4);
    mask_scan_kernel<<<Bdim, 256>>>(mask);

    // K1: QKV projection (fp16 1-term) + scatter
    {
        dim3 grid(H3 / 128, (Bdim * Sdim) / 128);
        gemm512_mma_kernel<0><<<grid, 256, GQ_SMEM>>>(p_x, p_wq, b_qkv, nullptr, H3);
    }
    // K2: scores on compacted key axis
    {
        dim3 grid(Sdim / 128, Sdim / 128, Bdim * NH);
        scores_mma_kernel<<<grid, 256, SC_SMEM>>>(pos);
    }
    // K2b: row inverse sums (active tiles only)
    rowsum_inv_kernel<<<(Bdim * NH * Sdim) / 256, 256>>>();

    // fork: pv (main, priority) ∥ mean (side, low priority)
    cudaEventRecord(ev_fork, 0);
    cudaStreamWaitEvent(s_side, ev_fork, 0);

    {
        dim3 grid(Sdim / 128, Bdim * NH);
        pv_mma_kernel<<<grid, 256, PV_SMEM_B>>>();
    }
    mean_kernel<<<Bdim * Sdim, 256, 0, s_side>>>(mean_out);
    cudaEventRecord(ev_join, s_side);

    // K5: output projection (fp16 1-term)
    {
        dim3 grid(Hdim / 128, (Bdim * Sdim) / 128);
        gemm512_mma_kernel<1><<<grid, 256, GQ_SMEM>>>(p_c, p_wo, b_out, out_proj, Hdim);
    }
    // join
    cudaStreamWaitEvent(0, ev_join, 0);
}